// round 1
// baseline (speedup 1.0000x reference)
#include <cuda_runtime.h>
#include <cuda_bf16.h>
#include <math.h>

// ---------------- problem constants ----------------
#define BB 4
#define CC 3
#define HH 224
#define WW 224
#define PP 16
#define EE 768
#define NHH 12
#define DHH 64
#define LL 2
#define DFF_ 3072
#define OUTC 1000
#define NPAT 196           // 14*14
#define TT 197             // 1 + NPAT
#define MROWS (BB*TT)      // 788
#define KPATCH (CC*PP*PP)  // 768

// ---------------- scratch (no allocation allowed) ----------------
__device__ float g_h[BB*TT*EE];
__device__ float g_ln[BB*TT*EE];
__device__ float g_qkv[BB*TT*3*EE];
__device__ float g_obuf[BB*TT*EE];
__device__ float g_mlp[BB*TT*DFF_];
__device__ float g_im2col[BB*NPAT*KPATCH];
__device__ float g_tok[BB*NPAT*EE];
__device__ float g_cls[BB*EE];

// ---------------- im2col for patch embedding ----------------
__global__ void im2col_kernel(const float* __restrict__ x) {
    int idx = blockIdx.x * blockDim.x + threadIdx.x;
    const int total = BB*NPAT*KPATCH;
    if (idx >= total) return;
    int k   = idx % KPATCH;
    int row = idx / KPATCH;
    int b = row / NPAT, t = row % NPAT;
    int ph = t / 14, pw = t % 14;
    int c = k / (PP*PP);
    int r = (k % (PP*PP)) / PP;
    int q = k % PP;
    g_im2col[idx] = x[(((size_t)(b*CC + c)*HH) + ph*PP + r) * WW + pw*PP + q];
}

// ---------------- assemble h = [cls; tok + pos] ----------------
__global__ void assemble_h_kernel(const float* __restrict__ pos_embed,
                                  const float* __restrict__ cls_token) {
    int idx = blockIdx.x * blockDim.x + threadIdx.x;
    const int total = BB*TT*EE;
    if (idx >= total) return;
    int e = idx % EE;
    int t = (idx / EE) % TT;
    int b = idx / (EE*TT);
    if (t == 0) {
        g_h[idx] = cls_token[e];
    } else {
        int pr = t - 1;
        g_h[idx] = g_tok[((size_t)(b*NPAT + pr))*EE + e] + pos_embed[(size_t)pr*EE + e];
    }
}

// ---------------- LayerNorm (block per row) ----------------
__global__ void ln_kernel(const float* __restrict__ in, const float* __restrict__ w,
                          const float* __restrict__ bch, float* __restrict__ out,
                          int cols, size_t in_stride, size_t out_stride) {
    int row = blockIdx.x;
    const float* x = in + (size_t)row * in_stride;
    float* y = out + (size_t)row * out_stride;
    __shared__ float red[256];
    int tid = threadIdx.x;

    float s = 0.f;
    for (int c = tid; c < cols; c += 256) s += x[c];
    red[tid] = s; __syncthreads();
    for (int st = 128; st > 0; st >>= 1) { if (tid < st) red[tid] += red[tid+st]; __syncthreads(); }
    float mu = red[0] / cols;
    __syncthreads();

    float s2 = 0.f;
    for (int c = tid; c < cols; c += 256) { float d = x[c] - mu; s2 += d*d; }
    red[tid] = s2; __syncthreads();
    for (int st = 128; st > 0; st >>= 1) { if (tid < st) red[tid] += red[tid+st]; __syncthreads(); }
    float inv = rsqrtf(red[0] / cols + 1e-5f);

    for (int c = tid; c < cols; c += 256)
        y[c] = (x[c] - mu) * inv * w[c] + bch[c];
}

// ---------------- generic tiled GEMM: C = act(A*B + bias) (+res) ----------------
// A: [M,K] row-major. B: row-major [K,N] (TB=false) or [N,K] (TB=true).
// ACT: 0 none, 1 tanh-gelu.
__device__ __forceinline__ float gelu_tanh(float v) {
    float v3 = v * v * v;
    return 0.5f * v * (1.0f + tanhf(0.7978845608028654f * (v + 0.044715f * v3)));
}

template<int ACT, bool TB, bool RES>
__global__ void gemm_kernel(const float* __restrict__ A, const float* __restrict__ B,
                            const float* __restrict__ bias, const float* __restrict__ res,
                            float* __restrict__ C, int M, int N, int K) {
    const int BM = 64, BN = 64, BK = 16;
    __shared__ float As[BK][BM + 1];
    __shared__ float Bs[BK][BN + 1];
    int bm = blockIdx.y * BM;
    int bn = blockIdx.x * BN;
    int tid = threadIdx.x;            // 256 threads
    int tx = tid & 15;                // 0..15
    int ty = tid >> 4;                // 0..15
    float acc[4][4];
    #pragma unroll
    for (int i = 0; i < 4; i++)
        #pragma unroll
        for (int j = 0; j < 4; j++) acc[i][j] = 0.f;

    for (int k0 = 0; k0 < K; k0 += BK) {
        // A tile: consecutive tid -> consecutive k (coalesced)
        #pragma unroll
        for (int i = 0; i < 4; i++) {
            int s = tid + i * 256;
            int m = s >> 4, kk = s & 15;
            int gm = bm + m, gk = k0 + kk;
            float v = 0.f;
            if (gm < M && gk < K) v = A[(size_t)gm * K + gk];
            As[kk][m] = v;
        }
        // B tile
        #pragma unroll
        for (int i = 0; i < 4; i++) {
            int s = tid + i * 256;
            if (!TB) {
                int kk = s >> 6, n = s & 63;   // consecutive tid -> consecutive n
                int gk = k0 + kk, gn = bn + n;
                float v = 0.f;
                if (gk < K && gn < N) v = B[(size_t)gk * N + gn];
                Bs[kk][n] = v;
            } else {
                int n = s >> 4, kk = s & 15;   // consecutive tid -> consecutive k
                int gk = k0 + kk, gn = bn + n;
                float v = 0.f;
                if (gk < K && gn < N) v = B[(size_t)gn * K + gk];
                Bs[kk][n] = v;
            }
        }
        __syncthreads();
        #pragma unroll
        for (int kk = 0; kk < BK; kk++) {
            float a[4], bvals[4];
            #pragma unroll
            for (int i = 0; i < 4; i++) a[i] = As[kk][ty * 4 + i];
            #pragma unroll
            for (int j = 0; j < 4; j++) bvals[j] = Bs[kk][tx * 4 + j];
            #pragma unroll
            for (int i = 0; i < 4; i++)
                #pragma unroll
                for (int j = 0; j < 4; j++)
                    acc[i][j] = fmaf(a[i], bvals[j], acc[i][j]);
        }
        __syncthreads();
    }

    #pragma unroll
    for (int i = 0; i < 4; i++) {
        int gm = bm + ty * 4 + i;
        if (gm >= M) continue;
        #pragma unroll
        for (int j = 0; j < 4; j++) {
            int gn = bn + tx * 4 + j;
            if (gn >= N) continue;
            float v = acc[i][j] + (bias ? bias[gn] : 0.f);
            if (ACT == 1) v = gelu_tanh(v);
            if (RES) v += res[(size_t)gm * N + gn];
            C[(size_t)gm * N + gn] = v;
        }
    }
}

// ---------------- fused Tversky attention row kernel ----------------
// One block per (b, h, i). Computes score row -> softmax -> P @ V row.
__global__ void attn_kernel(const float* __restrict__ qkv, float* __restrict__ obuf) {
    int blk = blockIdx.x;
    int i = blk % TT;
    int tmp = blk / TT;
    int h = tmp % NHH;
    int b = tmp / NHH;
    int tid = threadIdx.x;

    __shared__ float qp[DHH];
    __shared__ float sc[TT];
    __shared__ float red[256];
    __shared__ float qs_sh;

    const float* qrow = qkv + ((size_t)(b * TT + i)) * (3 * EE) + h * DHH;
    if (tid < DHH) qp[tid] = fmaxf(qrow[tid], 0.f);
    __syncthreads();
    if (tid == 0) {
        float s = 0.f;
        #pragma unroll
        for (int d = 0; d < DHH; d++) s += qp[d];
        qs_sh = s;
    }
    __syncthreads();
    float qs = qs_sh;

    if (tid < TT) {
        const float* krow = qkv + ((size_t)(b * TT + tid)) * (3 * EE) + EE + h * DHH;
        float l1 = 0.f, ks = 0.f;
        #pragma unroll 8
        for (int d = 0; d < DHH; d++) {
            float kp = fmaxf(krow[d], 0.f);
            ks += kp;
            l1 += fabsf(qp[d] - kp);
        }
        float inter = 0.5f * (qs + ks - l1);
        float amb   = 0.5f * (l1 + qs - ks);
        float bma   = 0.5f * (l1 - qs + ks);
        sc[tid] = inter / (inter + 0.5f * amb + 0.5f * bma + 1e-8f); // GAMMA=1
    }
    __syncthreads();

    // softmax: max
    float v = (tid < TT) ? sc[tid] : -INFINITY;
    red[tid] = v; __syncthreads();
    for (int s = 128; s > 0; s >>= 1) { if (tid < s) red[tid] = fmaxf(red[tid], red[tid+s]); __syncthreads(); }
    float mx = red[0];
    __syncthreads();

    float e = (tid < TT) ? expf(sc[tid] - mx) : 0.f;
    red[tid] = e; __syncthreads();
    for (int s = 128; s > 0; s >>= 1) { if (tid < s) red[tid] += red[tid+s]; __syncthreads(); }
    float denom = red[0];
    __syncthreads();
    if (tid < TT) sc[tid] = e / denom;
    __syncthreads();

    if (tid < DHH) {
        const float* vbase = qkv + (size_t)b * TT * (3 * EE) + 2 * EE + h * DHH + tid;
        float acc = 0.f;
        for (int j = 0; j < TT; j++) acc = fmaf(sc[j], vbase[(size_t)j * (3 * EE)], acc);
        obuf[((size_t)(b * TT + i)) * EE + h * DHH + tid] = acc;
    }
}

// ---------------- host launcher ----------------
static inline dim3 gemm_grid(int M, int N) { return dim3((N + 63) / 64, (M + 63) / 64); }

extern "C" void kernel_launch(void* const* d_in, const int* in_sizes, int n_in,
                              void* d_out, int out_size) {
    const float* x         = (const float*)d_in[0];
    const float* conv_w    = (const float*)d_in[1];
    const float* conv_b    = (const float*)d_in[2];
    const float* pos_embed = (const float*)d_in[3];
    const float* cls_token = (const float*)d_in[4];
    const float* ln1_w     = (const float*)d_in[5];
    const float* ln1_b     = (const float*)d_in[6];
    const float* attn_w    = (const float*)d_in[7];
    const float* attn_b    = (const float*)d_in[8];
    const float* proj_w    = (const float*)d_in[9];
    const float* proj_b    = (const float*)d_in[10];
    const float* ln2_w     = (const float*)d_in[11];
    const float* ln2_b     = (const float*)d_in[12];
    const float* fc1_w     = (const float*)d_in[13];
    const float* fc1_b     = (const float*)d_in[14];
    const float* fc2_w     = (const float*)d_in[15];
    const float* fc2_b     = (const float*)d_in[16];
    const float* lnf_w     = (const float*)d_in[17];
    const float* lnf_b     = (const float*)d_in[18];
    const float* head_w    = (const float*)d_in[19];
    const float* head_b    = (const float*)d_in[20];
    float* out = (float*)d_out;

    float *p_h, *p_ln, *p_qkv, *p_obuf, *p_mlp, *p_im2col, *p_tok, *p_cls;
    cudaGetSymbolAddress((void**)&p_h, g_h);
    cudaGetSymbolAddress((void**)&p_ln, g_ln);
    cudaGetSymbolAddress((void**)&p_qkv, g_qkv);
    cudaGetSymbolAddress((void**)&p_obuf, g_obuf);
    cudaGetSymbolAddress((void**)&p_mlp, g_mlp);
    cudaGetSymbolAddress((void**)&p_im2col, g_im2col);
    cudaGetSymbolAddress((void**)&p_tok, g_tok);
    cudaGetSymbolAddress((void**)&p_cls, g_cls);

    // 1) patch embedding: im2col -> GEMM (conv_w is [E, K] row-major => TB)
    {
        int total = BB*NPAT*KPATCH;
        im2col_kernel<<<(total + 255) / 256, 256>>>(x);
        gemm_kernel<0, true, false><<<gemm_grid(BB*NPAT, EE), 256>>>(
            p_im2col, conv_w, conv_b, nullptr, p_tok, BB*NPAT, EE, KPATCH);
        int th = BB*TT*EE;
        assemble_h_kernel<<<(th + 255) / 256, 256>>>(pos_embed, cls_token);
    }

    // 2) transformer layers
    for (int l = 0; l < LL; l++) {
        const float* lw1 = ln1_w + (size_t)l * EE;
        const float* lb1 = ln1_b + (size_t)l * EE;
        const float* aw  = attn_w + (size_t)l * EE * 3 * EE;
        const float* ab  = attn_b + (size_t)l * 3 * EE;
        const float* pw  = proj_w + (size_t)l * EE * EE;
        const float* pb  = proj_b + (size_t)l * EE;
        const float* lw2 = ln2_w + (size_t)l * EE;
        const float* lb2 = ln2_b + (size_t)l * EE;
        const float* f1w = fc1_w + (size_t)l * EE * DFF_;
        const float* f1b = fc1_b + (size_t)l * DFF_;
        const float* f2w = fc2_w + (size_t)l * DFF_ * EE;
        const float* f2b = fc2_b + (size_t)l * EE;

        ln_kernel<<<MROWS, 256>>>(p_h, lw1, lb1, p_ln, EE, EE, EE);
        gemm_kernel<0, false, false><<<gemm_grid(MROWS, 3*EE), 256>>>(
            p_ln, aw, ab, nullptr, p_qkv, MROWS, 3*EE, EE);
        attn_kernel<<<BB*NHH*TT, 256>>>(p_qkv, p_obuf);
        gemm_kernel<0, false, true><<<gemm_grid(MROWS, EE), 256>>>(
            p_obuf, pw, pb, p_h, p_h, MROWS, EE, EE);
        ln_kernel<<<MROWS, 256>>>(p_h, lw2, lb2, p_ln, EE, EE, EE);
        gemm_kernel<1, false, false><<<gemm_grid(MROWS, DFF_), 256>>>(
            p_ln, f1w, f1b, nullptr, p_mlp, MROWS, DFF_, EE);
        gemm_kernel<0, false, true><<<gemm_grid(MROWS, EE), 256>>>(
            p_mlp, f2w, f2b, p_h, p_h, MROWS, EE, DFF_);
    }

    // 3) final LN on cls rows only (row stride TT*EE) + head
    ln_kernel<<<BB, 256>>>(p_h, lnf_w, lnf_b, p_cls, EE, (size_t)TT*EE, EE);
    gemm_kernel<0, false, false><<<gemm_grid(BB, OUTC), 256>>>(
        p_cls, head_w, head_b, nullptr, out, BB, OUTC, EE);
}

// round 2
// speedup vs baseline: 1.2304x; 1.2304x over previous
#include <cuda_runtime.h>
#include <cuda_bf16.h>
#include <math.h>

// ---------------- problem constants ----------------
#define BB 4
#define CC 3
#define HH 224
#define WW 224
#define PP 16
#define EE 768
#define NHH 12
#define DHH 64
#define LL 2
#define DFF_ 3072
#define OUTC 1000
#define NPAT 196           // 14*14
#define TT 197             // 1 + NPAT
#define MROWS (BB*TT)      // 788
#define KPATCH (CC*PP*PP)  // 768

// ---------------- scratch (no allocation allowed) ----------------
__device__ float g_h[BB*TT*EE];
__device__ float g_ln[BB*TT*EE];
__device__ float g_qkv[BB*TT*3*EE];
__device__ float g_obuf[BB*TT*EE];
__device__ float g_mlp[BB*TT*DFF_];
__device__ float g_im2col[BB*NPAT*KPATCH];
__device__ float g_tok[BB*NPAT*EE];
__device__ float g_cls[BB*EE];
__device__ float g_part[4*MROWS*DFF_ > 4*MROWS*EE ? 4*MROWS*EE : 4*MROWS*EE]; // 4*788*768 partials
// (fc2/proj/patch all have N=768 output; 4 partials suffice)

// ---------------- im2col for patch embedding ----------------
__global__ void im2col_kernel(const float* __restrict__ x) {
    int idx = blockIdx.x * blockDim.x + threadIdx.x;
    const int total = BB*NPAT*KPATCH;
    if (idx >= total) return;
    int k   = idx % KPATCH;
    int row = idx / KPATCH;
    int b = row / NPAT, t = row % NPAT;
    int ph = t / 14, pw = t % 14;
    int c = k / (PP*PP);
    int r = (k % (PP*PP)) / PP;
    int q = k % PP;
    g_im2col[idx] = x[(((size_t)(b*CC + c)*HH) + ph*PP + r) * WW + pw*PP + q];
}

// ---------------- assemble h = [cls; tok + pos] ----------------
__global__ void assemble_h_kernel(const float* __restrict__ pos_embed,
                                  const float* __restrict__ cls_token) {
    int idx = blockIdx.x * blockDim.x + threadIdx.x;
    const int total = BB*TT*EE;
    if (idx >= total) return;
    int e = idx % EE;
    int t = (idx / EE) % TT;
    int b = idx / (EE*TT);
    if (t == 0) {
        g_h[idx] = cls_token[e];
    } else {
        int pr = t - 1;
        g_h[idx] = g_tok[((size_t)(b*NPAT + pr))*EE + e] + pos_embed[(size_t)pr*EE + e];
    }
}

// ---------------- LayerNorm (block per row) ----------------
__global__ void ln_kernel(const float* __restrict__ in, const float* __restrict__ w,
                          const float* __restrict__ bch, float* __restrict__ out,
                          int cols, size_t in_stride, size_t out_stride) {
    int row = blockIdx.x;
    const float* x = in + (size_t)row * in_stride;
    float* y = out + (size_t)row * out_stride;
    __shared__ float red[256];
    int tid = threadIdx.x;

    float s = 0.f;
    for (int c = tid; c < cols; c += 256) s += x[c];
    red[tid] = s; __syncthreads();
    for (int st = 128; st > 0; st >>= 1) { if (tid < st) red[tid] += red[tid+st]; __syncthreads(); }
    float mu = red[0] / cols;
    __syncthreads();

    float s2 = 0.f;
    for (int c = tid; c < cols; c += 256) { float d = x[c] - mu; s2 += d*d; }
    red[tid] = s2; __syncthreads();
    for (int st = 128; st > 0; st >>= 1) { if (tid < st) red[tid] += red[tid+st]; __syncthreads(); }
    float inv = rsqrtf(red[0] / cols + 1e-5f);

    for (int c = tid; c < cols; c += 256)
        y[c] = (x[c] - mu) * inv * w[c] + bch[c];
}

__device__ __forceinline__ float gelu_tanh(float v) {
    float v3 = v * v * v;
    return 0.5f * v * (1.0f + tanhf(0.7978845608028654f * (v + 0.044715f * v3)));
}

// ================= fast 128x128x8 double-buffered fp32 GEMM =================
// A: [M,K] row-major. B: [K,N] row-major (TB=false) or [N,K] row-major (TB=true).
// Requires: N % 128 == 0, K % 4 == 0, klen % 8 == 0. M guarded.
// grid = (N/128, ceil(M/128), S); split-K chunk z covers k in [z*klen, (z+1)*klen).
// PARTIAL: write raw partial sums to C + z*M*N (no epilogue).
template<int ACT, bool TB, bool RES, bool PARTIAL>
__global__ __launch_bounds__(256, 2)
void gemm128_kernel(const float* __restrict__ A, const float* __restrict__ B,
                    const float* __restrict__ bias, const float* __restrict__ res,
                    float* __restrict__ C, int M, int N, int K, int klen) {
    __shared__ float As[2][8][128];
    __shared__ float Bs[2][8][128];

    int bn = blockIdx.x * 128;
    int bm = blockIdx.y * 128;
    int kz = blockIdx.z * klen;
    if (PARTIAL) C += (size_t)blockIdx.z * M * N;

    int tid = threadIdx.x;
    int tx = tid & 15;
    int ty = tid >> 4;

    // A load mapping: 128 rows x 8 k, one float4 per thread
    int arow = tid >> 1;
    int akq  = (tid & 1) * 4;
    // B load mapping (TB=false): 8 k-rows x 128 n, one float4 per thread
    int bkk = tid >> 5;
    int bn4 = (tid & 31) * 4;
    // B load mapping (TB=true): like A
    int brow = tid >> 1;
    int bkq  = (tid & 1) * 4;

    float acc[8][8];
    #pragma unroll
    for (int i = 0; i < 8; i++)
        #pragma unroll
        for (int j = 0; j < 8; j++) acc[i][j] = 0.f;

    float4 ra, rb;
    int nk = klen >> 3;

    // ---- prologue: load stage 0 ----
    {
        int gm = bm + arow;
        ra = (gm < M) ? *(const float4*)(A + (size_t)gm * K + kz + akq)
                      : make_float4(0.f, 0.f, 0.f, 0.f);
        if (!TB) {
            rb = *(const float4*)(B + (size_t)(kz + bkk) * N + bn + bn4);
        } else {
            rb = *(const float4*)(B + (size_t)(bn + brow) * K + kz + bkq);
        }
        As[0][akq + 0][arow] = ra.x;
        As[0][akq + 1][arow] = ra.y;
        As[0][akq + 2][arow] = ra.z;
        As[0][akq + 3][arow] = ra.w;
        if (!TB) {
            *(float4*)&Bs[0][bkk][bn4] = rb;
        } else {
            Bs[0][bkq + 0][brow] = rb.x;
            Bs[0][bkq + 1][brow] = rb.y;
            Bs[0][bkq + 2][brow] = rb.z;
            Bs[0][bkq + 3][brow] = rb.w;
        }
    }
    __syncthreads();

    int buf = 0;
    for (int kt = 0; kt < nk; kt++) {
        // prefetch next stage into registers
        if (kt + 1 < nk) {
            int k0 = kz + (kt + 1) * 8;
            int gm = bm + arow;
            ra = (gm < M) ? *(const float4*)(A + (size_t)gm * K + k0 + akq)
                          : make_float4(0.f, 0.f, 0.f, 0.f);
            if (!TB) {
                rb = *(const float4*)(B + (size_t)(k0 + bkk) * N + bn + bn4);
            } else {
                rb = *(const float4*)(B + (size_t)(bn + brow) * K + k0 + bkq);
            }
        }
        // compute on current buffer
        #pragma unroll
        for (int kk = 0; kk < 8; kk++) {
            float a[8], bv[8];
            *(float4*)(a)     = *(const float4*)&As[buf][kk][ty * 4];
            *(float4*)(a + 4) = *(const float4*)&As[buf][kk][64 + ty * 4];
            *(float4*)(bv)     = *(const float4*)&Bs[buf][kk][tx * 4];
            *(float4*)(bv + 4) = *(const float4*)&Bs[buf][kk][64 + tx * 4];
            #pragma unroll
            for (int i = 0; i < 8; i++)
                #pragma unroll
                for (int j = 0; j < 8; j++)
                    acc[i][j] = fmaf(a[i], bv[j], acc[i][j]);
        }
        // store prefetched stage to other buffer
        if (kt + 1 < nk) {
            int nb = buf ^ 1;
            As[nb][akq + 0][arow] = ra.x;
            As[nb][akq + 1][arow] = ra.y;
            As[nb][akq + 2][arow] = ra.z;
            As[nb][akq + 3][arow] = ra.w;
            if (!TB) {
                *(float4*)&Bs[nb][bkk][bn4] = rb;
            } else {
                Bs[nb][bkq + 0][brow] = rb.x;
                Bs[nb][bkq + 1][brow] = rb.y;
                Bs[nb][bkq + 2][brow] = rb.z;
                Bs[nb][bkq + 3][brow] = rb.w;
            }
            __syncthreads();
            buf = nb;
        }
    }

    // ---- epilogue ----
    #pragma unroll
    for (int i = 0; i < 8; i++) {
        int gm = bm + (i < 4 ? ty * 4 + i : 64 + ty * 4 + (i - 4));
        if (gm >= M) continue;
        #pragma unroll
        for (int j = 0; j < 8; j++) {
            int gn = bn + (j < 4 ? tx * 4 + j : 64 + tx * 4 + (j - 4));
            float v = acc[i][j];
            if (!PARTIAL) {
                v += bias[gn];
                if (ACT == 1) v = gelu_tanh(v);
                if (RES) v += res[(size_t)gm * N + gn];
            }
            C[(size_t)gm * N + gn] = v;
        }
    }
}

// ---------------- split-K reduce + bias (+res) epilogue ----------------
template<bool RES>
__global__ void reduce_kernel(const float* __restrict__ part, int S,
                              const float* __restrict__ bias,
                              const float* __restrict__ res,
                              float* __restrict__ out, int MN, int N) {
    int idx = blockIdx.x * blockDim.x + threadIdx.x;
    if (idx >= MN) return;
    float s = 0.f;
    for (int p = 0; p < S; p++) s += part[(size_t)p * MN + idx];
    s += bias[idx % N];
    if (RES) s += res[idx];
    out[idx] = s;
}

// ---------------- small bounds-checked GEMM (head only) ----------------
template<int ACT, bool TB, bool RES>
__global__ void gemm_kernel(const float* __restrict__ A, const float* __restrict__ B,
                            const float* __restrict__ bias, const float* __restrict__ res,
                            float* __restrict__ C, int M, int N, int K) {
    const int BM = 64, BN = 64, BK = 16;
    __shared__ float As[BK][BM + 1];
    __shared__ float Bs[BK][BN + 1];
    int bm = blockIdx.y * BM;
    int bn = blockIdx.x * BN;
    int tid = threadIdx.x;
    int tx = tid & 15;
    int ty = tid >> 4;
    float acc[4][4];
    #pragma unroll
    for (int i = 0; i < 4; i++)
        #pragma unroll
        for (int j = 0; j < 4; j++) acc[i][j] = 0.f;

    for (int k0 = 0; k0 < K; k0 += BK) {
        #pragma unroll
        for (int i = 0; i < 4; i++) {
            int s = tid + i * 256;
            int m = s >> 4, kk = s & 15;
            int gm = bm + m, gk = k0 + kk;
            float v = 0.f;
            if (gm < M && gk < K) v = A[(size_t)gm * K + gk];
            As[kk][m] = v;
        }
        #pragma unroll
        for (int i = 0; i < 4; i++) {
            int s = tid + i * 256;
            if (!TB) {
                int kk = s >> 6, n = s & 63;
                int gk = k0 + kk, gn = bn + n;
                float v = 0.f;
                if (gk < K && gn < N) v = B[(size_t)gk * N + gn];
                Bs[kk][n] = v;
            } else {
                int n = s >> 4, kk = s & 15;
                int gk = k0 + kk, gn = bn + n;
                float v = 0.f;
                if (gk < K && gn < N) v = B[(size_t)gn * K + gk];
                Bs[kk][n] = v;
            }
        }
        __syncthreads();
        #pragma unroll
        for (int kk = 0; kk < BK; kk++) {
            float a[4], bvals[4];
            #pragma unroll
            for (int i = 0; i < 4; i++) a[i] = As[kk][ty * 4 + i];
            #pragma unroll
            for (int j = 0; j < 4; j++) bvals[j] = Bs[kk][tx * 4 + j];
            #pragma unroll
            for (int i = 0; i < 4; i++)
                #pragma unroll
                for (int j = 0; j < 4; j++)
                    acc[i][j] = fmaf(a[i], bvals[j], acc[i][j]);
        }
        __syncthreads();
    }

    #pragma unroll
    for (int i = 0; i < 4; i++) {
        int gm = bm + ty * 4 + i;
        if (gm >= M) continue;
        #pragma unroll
        for (int j = 0; j < 4; j++) {
            int gn = bn + tx * 4 + j;
            if (gn >= N) continue;
            float v = acc[i][j] + (bias ? bias[gn] : 0.f);
            if (ACT == 1) v = gelu_tanh(v);
            if (RES) v += res[(size_t)gm * N + gn];
            C[(size_t)gm * N + gn] = v;
        }
    }
}

// ---------------- fused Tversky attention row kernel ----------------
__global__ void attn_kernel(const float* __restrict__ qkv, float* __restrict__ obuf) {
    int blk = blockIdx.x;
    int i = blk % TT;
    int tmp = blk / TT;
    int h = tmp % NHH;
    int b = tmp / NHH;
    int tid = threadIdx.x;

    __shared__ float qp[DHH];
    __shared__ float sc[TT];
    __shared__ float red[256];
    __shared__ float qs_sh;

    const float* qrow = qkv + ((size_t)(b * TT + i)) * (3 * EE) + h * DHH;
    if (tid < DHH) qp[tid] = fmaxf(qrow[tid], 0.f);
    __syncthreads();
    if (tid == 0) {
        float s = 0.f;
        #pragma unroll
        for (int d = 0; d < DHH; d++) s += qp[d];
        qs_sh = s;
    }
    __syncthreads();
    float qs = qs_sh;

    if (tid < TT) {
        const float* krow = qkv + ((size_t)(b * TT + tid)) * (3 * EE) + EE + h * DHH;
        float l1 = 0.f, ks = 0.f;
        #pragma unroll 8
        for (int d = 0; d < DHH; d++) {
            float kp = fmaxf(krow[d], 0.f);
            ks += kp;
            l1 += fabsf(qp[d] - kp);
        }
        float inter = 0.5f * (qs + ks - l1);
        float amb   = 0.5f * (l1 + qs - ks);
        float bma   = 0.5f * (l1 - qs + ks);
        sc[tid] = inter / (inter + 0.5f * amb + 0.5f * bma + 1e-8f);
    }
    __syncthreads();

    float v = (tid < TT) ? sc[tid] : -INFINITY;
    red[tid] = v; __syncthreads();
    for (int s = 128; s > 0; s >>= 1) { if (tid < s) red[tid] = fmaxf(red[tid], red[tid+s]); __syncthreads(); }
    float mx = red[0];
    __syncthreads();

    float e = (tid < TT) ? expf(sc[tid] - mx) : 0.f;
    red[tid] = e; __syncthreads();
    for (int s = 128; s > 0; s >>= 1) { if (tid < s) red[tid] += red[tid+s]; __syncthreads(); }
    float denom = red[0];
    __syncthreads();
    if (tid < TT) sc[tid] = e / denom;
    __syncthreads();

    if (tid < DHH) {
        const float* vbase = qkv + (size_t)b * TT * (3 * EE) + 2 * EE + h * DHH + tid;
        float acc = 0.f;
        for (int j = 0; j < TT; j++) acc = fmaf(sc[j], vbase[(size_t)j * (3 * EE)], acc);
        obuf[((size_t)(b * TT + i)) * EE + h * DHH + tid] = acc;
    }
}

// ---------------- host launcher ----------------
extern "C" void kernel_launch(void* const* d_in, const int* in_sizes, int n_in,
                              void* d_out, int out_size) {
    const float* x         = (const float*)d_in[0];
    const float* conv_w    = (const float*)d_in[1];
    const float* conv_b    = (const float*)d_in[2];
    const float* pos_embed = (const float*)d_in[3];
    const float* cls_token = (const float*)d_in[4];
    const float* ln1_w     = (const float*)d_in[5];
    const float* ln1_b     = (const float*)d_in[6];
    const float* attn_w    = (const float*)d_in[7];
    const float* attn_b    = (const float*)d_in[8];
    const float* proj_w    = (const float*)d_in[9];
    const float* proj_b    = (const float*)d_in[10];
    const float* ln2_w     = (const float*)d_in[11];
    const float* ln2_b     = (const float*)d_in[12];
    const float* fc1_w     = (const float*)d_in[13];
    const float* fc1_b     = (const float*)d_in[14];
    const float* fc2_w     = (const float*)d_in[15];
    const float* fc2_b     = (const float*)d_in[16];
    const float* lnf_w     = (const float*)d_in[17];
    const float* lnf_b     = (const float*)d_in[18];
    const float* head_w    = (const float*)d_in[19];
    const float* head_b    = (const float*)d_in[20];
    float* out = (float*)d_out;

    float *p_h, *p_ln, *p_qkv, *p_obuf, *p_mlp, *p_im2col, *p_tok, *p_cls, *p_part;
    cudaGetSymbolAddress((void**)&p_h, g_h);
    cudaGetSymbolAddress((void**)&p_ln, g_ln);
    cudaGetSymbolAddress((void**)&p_qkv, g_qkv);
    cudaGetSymbolAddress((void**)&p_obuf, g_obuf);
    cudaGetSymbolAddress((void**)&p_mlp, g_mlp);
    cudaGetSymbolAddress((void**)&p_im2col, g_im2col);
    cudaGetSymbolAddress((void**)&p_tok, g_tok);
    cudaGetSymbolAddress((void**)&p_cls, g_cls);
    cudaGetSymbolAddress((void**)&p_part, g_part);

    // 1) patch embedding: im2col -> split-K GEMM (conv_w is [E,K] => TB) -> reduce
    {
        int total = BB*NPAT*KPATCH;
        im2col_kernel<<<(total + 255) / 256, 256>>>(x);
        dim3 g(EE/128, (BB*NPAT + 127)/128, 4);
        gemm128_kernel<0, true, false, true><<<g, 256>>>(
            p_im2col, conv_w, nullptr, nullptr, p_part, BB*NPAT, EE, KPATCH, KPATCH/4);
        int mn = BB*NPAT*EE;
        reduce_kernel<false><<<(mn + 255)/256, 256>>>(p_part, 4, conv_b, nullptr, p_tok, mn, EE);
        int th = BB*TT*EE;
        assemble_h_kernel<<<(th + 255) / 256, 256>>>(pos_embed, cls_token);
    }

    // 2) transformer layers
    for (int l = 0; l < LL; l++) {
        const float* lw1 = ln1_w + (size_t)l * EE;
        const float* lb1 = ln1_b + (size_t)l * EE;
        const float* aw  = attn_w + (size_t)l * EE * 3 * EE;
        const float* ab  = attn_b + (size_t)l * 3 * EE;
        const float* pw  = proj_w + (size_t)l * EE * EE;
        const float* pb  = proj_b + (size_t)l * EE;
        const float* lw2 = ln2_w + (size_t)l * EE;
        const float* lb2 = ln2_b + (size_t)l * EE;
        const float* f1w = fc1_w + (size_t)l * EE * DFF_;
        const float* f1b = fc1_b + (size_t)l * DFF_;
        const float* f2w = fc2_w + (size_t)l * DFF_ * EE;
        const float* f2b = fc2_b + (size_t)l * EE;

        ln_kernel<<<MROWS, 256>>>(p_h, lw1, lb1, p_ln, EE, EE, EE);

        // qkv: direct epilogue (bias), 126 blocks
        {
            dim3 g((3*EE)/128, (MROWS + 127)/128, 1);
            gemm128_kernel<0, false, false, false><<<g, 256>>>(
                p_ln, aw, ab, nullptr, p_qkv, MROWS, 3*EE, EE, EE);
        }

        attn_kernel<<<BB*NHH*TT, 256>>>(p_qkv, p_obuf);

        // proj: split-K=4 + reduce(bias, res=h) -> h
        {
            dim3 g(EE/128, (MROWS + 127)/128, 4);
            gemm128_kernel<0, false, false, true><<<g, 256>>>(
                p_obuf, pw, nullptr, nullptr, p_part, MROWS, EE, EE, EE/4);
            int mn = MROWS*EE;
            reduce_kernel<true><<<(mn + 255)/256, 256>>>(p_part, 4, pb, p_h, p_h, mn, EE);
        }

        ln_kernel<<<MROWS, 256>>>(p_h, lw2, lb2, p_ln, EE, EE, EE);

        // fc1: direct epilogue (bias + gelu), 168 blocks
        {
            dim3 g(DFF_/128, (MROWS + 127)/128, 1);
            gemm128_kernel<1, false, false, false><<<g, 256>>>(
                p_ln, f1w, f1b, nullptr, p_mlp, MROWS, DFF_, EE, EE);
        }

        // fc2: split-K=4 + reduce(bias, res=h) -> h
        {
            dim3 g(EE/128, (MROWS + 127)/128, 4);
            gemm128_kernel<0, false, false, true><<<g, 256>>>(
                p_mlp, f2w, nullptr, nullptr, p_part, MROWS, EE, DFF_, DFF_/4);
            int mn = MROWS*EE;
            reduce_kernel<true><<<(mn + 255)/256, 256>>>(p_part, 4, f2b, p_h, p_h, mn, EE);
        }
    }

    // 3) final LN on cls rows only + head
    ln_kernel<<<BB, 256>>>(p_h, lnf_w, lnf_b, p_cls, EE, (size_t)TT*EE, EE);
    gemm_kernel<0, false, false><<<dim3((OUTC + 63)/64, 1), 256>>>(
        p_cls, head_w, head_b, nullptr, out, BB, OUTC, EE);
}

// round 3
// speedup vs baseline: 3.1038x; 2.5225x over previous
#include <cuda_runtime.h>
#include <cuda_bf16.h>
#include <math.h>
#include <stdint.h>

// ---------------- problem constants ----------------
#define BB 4
#define CC 3
#define HH 224
#define WW 224
#define PP 16
#define EE 768
#define NHH 12
#define DHH 64
#define LL 2
#define DFF_ 3072
#define OUTC 1000
#define NPAT 196
#define TT 197
#define MROWS (BB*TT)      // 788
#define KPATCH (CC*PP*PP)  // 768

// ---------------- scratch ----------------
__device__ float g_h[BB*TT*EE];
__device__ float g_qkv[BB*TT*3*EE];
__device__ float g_tok[BB*NPAT*EE];
__device__ float g_cls[BB*EE];
__device__ float g_part[8*MROWS*EE];
__device__ float g_kT[BB*NHH*DHH*256];
__device__ __nv_bfloat16 g_abf[MROWS*3*DFF_];   // 788 x 9216 (im2col tri / obuf tri / fc1 tri)
__device__ __nv_bfloat16 g_wbf[3*DFF_*EE];      // up to 9216 x 768 / 2304 x 3072
__device__ __nv_bfloat16 g_lntri[MROWS*3*EE];   // 788 x 2304

// ---------------- helpers ----------------
__device__ __forceinline__ uint32_t smaddr(const void* p) {
    return (uint32_t)__cvta_generic_to_shared(p);
}
__device__ __forceinline__ void ldsm_x4(uint32_t& r0, uint32_t& r1, uint32_t& r2, uint32_t& r3, uint32_t a) {
    asm volatile("ldmatrix.sync.aligned.m8n8.x4.shared.b16 {%0,%1,%2,%3}, [%4];"
                 : "=r"(r0), "=r"(r1), "=r"(r2), "=r"(r3) : "r"(a));
}
__device__ __forceinline__ void ldsm_x4_t(uint32_t& r0, uint32_t& r1, uint32_t& r2, uint32_t& r3, uint32_t a) {
    asm volatile("ldmatrix.sync.aligned.m8n8.x4.trans.shared.b16 {%0,%1,%2,%3}, [%4];"
                 : "=r"(r0), "=r"(r1), "=r"(r2), "=r"(r3) : "r"(a));
}
__device__ __forceinline__ void mma_bf16(float* c, uint32_t a0, uint32_t a1, uint32_t a2, uint32_t a3,
                                         uint32_t b0, uint32_t b1) {
    asm volatile("mma.sync.aligned.m16n8k16.row.col.f32.bf16.bf16.f32 "
                 "{%0,%1,%2,%3}, {%4,%5,%6,%7}, {%8,%9}, {%0,%1,%2,%3};"
                 : "+f"(c[0]), "+f"(c[1]), "+f"(c[2]), "+f"(c[3])
                 : "r"(a0), "r"(a1), "r"(a2), "r"(a3), "r"(b0), "r"(b1));
}
__device__ __forceinline__ float gelu_tanh(float v) {
    float v3 = v * v * v;
    return 0.5f * v * (1.0f + tanhf(0.7978845608028654f * (v + 0.044715f * v3)));
}
__device__ __forceinline__ void split_bf16(float v, __nv_bfloat16& hi, __nv_bfloat16& lo) {
    hi = __float2bfloat16(v);
    lo = __float2bfloat16(v - __bfloat162float(hi));
}

// ---------------- im2col -> bf16 triple [784, 3*768] ----------------
__global__ void im2col_tri_kernel(const float* __restrict__ x, __nv_bfloat16* __restrict__ out) {
    int idx = blockIdx.x * blockDim.x + threadIdx.x;
    const int total = BB*NPAT*KPATCH;
    if (idx >= total) return;
    int k   = idx % KPATCH;
    int row = idx / KPATCH;
    int b = row / NPAT, t = row % NPAT;
    int ph = t / 14, pw = t % 14;
    int c = k / (PP*PP);
    int r = (k % (PP*PP)) / PP;
    int q = k % PP;
    float v = x[(((size_t)(b*CC + c)*HH) + ph*PP + r) * WW + pw*PP + q];
    __nv_bfloat16 hi, lo; split_bf16(v, hi, lo);
    __nv_bfloat16* o = out + (size_t)row * (3*KPATCH);
    o[k] = hi; o[KPATCH + k] = lo; o[2*KPATCH + k] = hi;
}

// ---------------- weight fp32 [K,N] -> bf16 triple [3K, N] ----------------
__global__ void wconv_std_kernel(const float* __restrict__ W, __nv_bfloat16* __restrict__ out, int K, int N) {
    int idx = blockIdx.x * blockDim.x + threadIdx.x;
    if (idx >= K * N) return;
    int k = idx / N, n = idx % N;
    __nv_bfloat16 hi, lo; split_bf16(W[idx], hi, lo);
    out[(size_t)k*N + n] = hi;
    out[(size_t)(K + k)*N + n] = hi;
    out[(size_t)(2*K + k)*N + n] = lo;
}
// weight fp32 [N,K] (transposed) -> bf16 triple [3K, N]
__global__ void wconv_t_kernel(const float* __restrict__ W, __nv_bfloat16* __restrict__ out, int K, int N) {
    int idx = blockIdx.x * blockDim.x + threadIdx.x;
    if (idx >= K * N) return;
    int k = idx / N, n = idx % N;
    __nv_bfloat16 hi, lo; split_bf16(W[(size_t)n*K + k], hi, lo);
    out[(size_t)k*N + n] = hi;
    out[(size_t)(K + k)*N + n] = hi;
    out[(size_t)(2*K + k)*N + n] = lo;
}

// ---------------- assemble h = [cls; tok + pos] ----------------
__global__ void assemble_h_kernel(const float* __restrict__ pos_embed,
                                  const float* __restrict__ cls_token) {
    int idx = blockIdx.x * blockDim.x + threadIdx.x;
    const int total = BB*TT*EE;
    if (idx >= total) return;
    int e = idx % EE;
    int t = (idx / EE) % TT;
    int b = idx / (EE*TT);
    if (t == 0) g_h[idx] = cls_token[e];
    else {
        int pr = t - 1;
        g_h[idx] = g_tok[((size_t)(b*NPAT + pr))*EE + e] + pos_embed[(size_t)pr*EE + e];
    }
}

// ---------------- LayerNorm fp32 out ----------------
__global__ void ln_kernel(const float* __restrict__ in, const float* __restrict__ w,
                          const float* __restrict__ bch, float* __restrict__ out,
                          int cols, size_t in_stride, size_t out_stride) {
    int row = blockIdx.x;
    const float* x = in + (size_t)row * in_stride;
    float* y = out + (size_t)row * out_stride;
    __shared__ float red[256];
    int tid = threadIdx.x;
    float s = 0.f;
    for (int c = tid; c < cols; c += 256) s += x[c];
    red[tid] = s; __syncthreads();
    for (int st = 128; st > 0; st >>= 1) { if (tid < st) red[tid] += red[tid+st]; __syncthreads(); }
    float mu = red[0] / cols; __syncthreads();
    float s2 = 0.f;
    for (int c = tid; c < cols; c += 256) { float d = x[c] - mu; s2 += d*d; }
    red[tid] = s2; __syncthreads();
    for (int st = 128; st > 0; st >>= 1) { if (tid < st) red[tid] += red[tid+st]; __syncthreads(); }
    float inv = rsqrtf(red[0] / cols + 1e-5f);
    for (int c = tid; c < cols; c += 256)
        y[c] = (x[c] - mu) * inv * w[c] + bch[c];
}

// ---------------- LayerNorm -> bf16 triple [row, 3*EE] ----------------
__global__ void ln_tri_kernel(const float* __restrict__ in, const float* __restrict__ w,
                              const float* __restrict__ bch, __nv_bfloat16* __restrict__ out) {
    int row = blockIdx.x;
    const float* x = in + (size_t)row * EE;
    __nv_bfloat16* y = out + (size_t)row * (3*EE);
    __shared__ float red[256];
    int tid = threadIdx.x;
    float s = 0.f;
    for (int c = tid; c < EE; c += 256) s += x[c];
    red[tid] = s; __syncthreads();
    for (int st = 128; st > 0; st >>= 1) { if (tid < st) red[tid] += red[tid+st]; __syncthreads(); }
    float mu = red[0] / EE; __syncthreads();
    float s2 = 0.f;
    for (int c = tid; c < EE; c += 256) { float d = x[c] - mu; s2 += d*d; }
    red[tid] = s2; __syncthreads();
    for (int st = 128; st > 0; st >>= 1) { if (tid < st) red[tid] += red[tid+st]; __syncthreads(); }
    float inv = rsqrtf(red[0] / EE + 1e-5f);
    for (int c = tid; c < EE; c += 256) {
        float v = (x[c] - mu) * inv * w[c] + bch[c];
        __nv_bfloat16 hi, lo; split_bf16(v, hi, lo);
        y[c] = hi; y[EE + c] = lo; y[2*EE + c] = hi;
    }
}

// ================= bf16 tensor-core GEMM (mma.sync m16n8k16) =================
// A': [M, Ka] bf16 row-major.  B': [Ka, N] bf16 row-major.  BM=128 BN=64 BK=32.
// grid = (N/64, ceil(M/128), S). PARTIAL: raw partials to C + z*M*N.
// TRIPLE: write act(v)+bias (+res) as bf16 triple rows of width 3N into Ctri.
template<int ACT, bool PARTIAL, bool RES, bool TRIPLE>
__global__ __launch_bounds__(256)
void mma_gemm(const __nv_bfloat16* __restrict__ A, const __nv_bfloat16* __restrict__ B,
              const float* __restrict__ bias, const float* __restrict__ res,
              float* __restrict__ C, __nv_bfloat16* __restrict__ Ctri,
              int M, int N, int Ka, int klen) {
    __shared__ __nv_bfloat16 As[2][128*40];   // row stride 40 (pad 8)
    __shared__ __nv_bfloat16 Bs[2][32*72];    // row stride 72 (pad 8)

    int bn = blockIdx.x * 64;
    int bm = blockIdx.y * 128;
    int kz = blockIdx.z * klen;
    int tid = threadIdx.x;
    int lane = tid & 31;
    int w = tid >> 5;
    int wm = (w & 3) * 32;   // 4 m-warps
    int wn = (w >> 2) * 32;  // 2 n-warps

    int ar0 = tid >> 2;              // 0..63
    int ar1 = ar0 + 64;              // 64..127
    int as0 = (tid & 3) * 8;
    int brow = tid >> 3;             // 0..31
    int bseg = (tid & 7) * 8;

    float acc[2][4][4];
    #pragma unroll
    for (int i = 0; i < 2; i++)
        #pragma unroll
        for (int j = 0; j < 4; j++)
            #pragma unroll
            for (int k = 0; k < 4; k++) acc[i][j][k] = 0.f;

    uint4 ra0, ra1, rb;
    const uint4 zero4 = make_uint4(0, 0, 0, 0);

    auto fetch = [&](int kt) {
        int k0 = kz + kt * 32;
        int gm0 = bm + ar0, gm1 = bm + ar1;
        ra0 = (gm0 < M) ? *(const uint4*)(A + (size_t)gm0 * Ka + k0 + as0) : zero4;
        ra1 = (gm1 < M) ? *(const uint4*)(A + (size_t)gm1 * Ka + k0 + as0) : zero4;
        rb  = *(const uint4*)(B + (size_t)(k0 + brow) * N + bn + bseg);
    };
    auto stash = [&](int b) {
        *(uint4*)&As[b][ar0*40 + as0] = ra0;
        *(uint4*)&As[b][ar1*40 + as0] = ra1;
        *(uint4*)&Bs[b][brow*72 + bseg] = rb;
    };

    fetch(0); stash(0); __syncthreads();
    int nk = klen >> 5;
    int buf = 0;
    for (int kt = 0; kt < nk; kt++) {
        if (kt + 1 < nk) fetch(kt + 1);
        #pragma unroll
        for (int s = 0; s < 2; s++) {
            uint32_t a[2][4], bf[4][2];
            #pragma unroll
            for (int mt = 0; mt < 2; mt++) {
                uint32_t ad = smaddr(&As[buf][(wm + mt*16 + (lane & 15))*40 + s*16 + (lane >> 4)*8]);
                ldsm_x4(a[mt][0], a[mt][1], a[mt][2], a[mt][3], ad);
            }
            #pragma unroll
            for (int h2 = 0; h2 < 2; h2++) {
                uint32_t ad = smaddr(&Bs[buf][(s*16 + (lane & 15))*72 + wn + h2*16 + (lane >> 4)*8]);
                ldsm_x4_t(bf[h2*2][0], bf[h2*2][1], bf[h2*2+1][0], bf[h2*2+1][1], ad);
            }
            #pragma unroll
            for (int mt = 0; mt < 2; mt++)
                #pragma unroll
                for (int nt = 0; nt < 4; nt++)
                    mma_bf16(acc[mt][nt], a[mt][0], a[mt][1], a[mt][2], a[mt][3],
                             bf[nt][0], bf[nt][1]);
        }
        if (kt + 1 < nk) { buf ^= 1; stash(buf); __syncthreads(); }
    }

    // epilogue
    #pragma unroll
    for (int mt = 0; mt < 2; mt++) {
        int rbase = bm + wm + mt*16 + (lane >> 2);
        #pragma unroll
        for (int nt = 0; nt < 4; nt++) {
            int cbase = bn + wn + nt*8 + (lane & 3)*2;
            #pragma unroll
            for (int half = 0; half < 2; half++) {
                int gm = rbase + half*8;
                if (gm >= M) continue;
                #pragma unroll
                for (int e = 0; e < 2; e++) {
                    int gn = cbase + e;
                    float v = acc[mt][nt][half*2 + e];
                    if (PARTIAL) {
                        C[(size_t)blockIdx.z * M * N + (size_t)gm * N + gn] = v;
                    } else {
                        v += bias[gn];
                        if (ACT == 1) v = gelu_tanh(v);
                        if (RES) v += res[(size_t)gm * N + gn];
                        if (TRIPLE) {
                            __nv_bfloat16 hi, lo; split_bf16(v, hi, lo);
                            __nv_bfloat16* o = Ctri + (size_t)gm * (3*N);
                            o[gn] = hi; o[N + gn] = lo; o[2*N + gn] = hi;
                        } else {
                            C[(size_t)gm * N + gn] = v;
                        }
                    }
                }
            }
        }
    }
}

// ---------------- split-K reduce + bias (+res) ----------------
template<bool RES>
__global__ void reduce_kernel(const float* __restrict__ part, int S,
                              const float* __restrict__ bias,
                              const float* __restrict__ res,
                              float* __restrict__ out, int MN, int N) {
    int idx = blockIdx.x * blockDim.x + threadIdx.x;
    if (idx >= MN) return;
    float s = 0.f;
    for (int p = 0; p < S; p++) s += part[(size_t)p * MN + idx];
    s += bias[idx % N];
    if (RES) s += res[idx];
    out[idx] = s;
}

// ---------------- K prep: relu + transpose -> kT[bh][d][j] (stride 256) ------
__global__ void kprep_kernel(const float* __restrict__ qkv) {
    int bh = blockIdx.x;          // 0..47
    int jt = blockIdx.y;          // 0..3
    int b = bh / NHH, h = bh % NHH;
    __shared__ float sm[64][65];
    int tid = threadIdx.x;
    #pragma unroll
    for (int p = 0; p < 16; p++) {
        int idx = tid + p * 256;
        int jj = idx >> 6, d = idx & 63;
        int j = jt * 64 + jj;
        float v = 0.f;
        if (j < TT) v = fmaxf(qkv[((size_t)(b*TT + j))*(3*EE) + EE + h*DHH + d], 0.f);
        sm[jj][d] = v;
    }
    __syncthreads();
    #pragma unroll
    for (int p = 0; p < 16; p++) {
        int idx = tid + p * 256;
        int d = idx >> 6, jj = idx & 63;
        g_kT[((size_t)bh*DHH + d)*256 + jt*64 + jj] = sm[jj][d];
    }
}

// ---------------- fused Tversky attention (triple-out) ----------------
__global__ void attn_kernel(const float* __restrict__ qkv, __nv_bfloat16* __restrict__ otri) {
    int blk = blockIdx.x;
    int i = blk % TT;
    int tmp = blk / TT;
    int h = tmp % NHH;
    int b = tmp / NHH;
    int bh = b * NHH + h;
    int tid = threadIdx.x;

    __shared__ float qp[DHH];
    __shared__ float sc[TT];
    __shared__ float red[256];
    __shared__ float part[4][DHH];
    __shared__ float qs_sh;

    const float* qrow = qkv + ((size_t)(b*TT + i))*(3*EE) + h*DHH;
    if (tid < DHH) qp[tid] = fmaxf(qrow[tid], 0.f);
    __syncthreads();
    if (tid == 0) {
        float s = 0.f;
        #pragma unroll
        for (int d = 0; d < DHH; d++) s += qp[d];
        qs_sh = s;
    }
    __syncthreads();
    float qs = qs_sh;

    if (tid < TT) {
        const float* kcol = g_kT + (size_t)bh * DHH * 256 + tid;
        float l1 = 0.f, ks = 0.f;
        #pragma unroll 8
        for (int d = 0; d < DHH; d++) {
            float kp = kcol[(size_t)d * 256];
            ks += kp;
            l1 += fabsf(qp[d] - kp);
        }
        float inter = 0.5f * (qs + ks - l1);
        float amb   = 0.5f * (l1 + qs - ks);
        float bma   = 0.5f * (l1 - qs + ks);
        sc[tid] = inter / (inter + 0.5f * amb + 0.5f * bma + 1e-8f);
    }
    __syncthreads();

    float v = (tid < TT) ? sc[tid] : -INFINITY;
    red[tid] = v; __syncthreads();
    for (int s = 128; s > 0; s >>= 1) { if (tid < s) red[tid] = fmaxf(red[tid], red[tid+s]); __syncthreads(); }
    float mx = red[0]; __syncthreads();
    float e = (tid < TT) ? expf(sc[tid] - mx) : 0.f;
    red[tid] = e; __syncthreads();
    for (int s = 128; s > 0; s >>= 1) { if (tid < s) red[tid] += red[tid+s]; __syncthreads(); }
    float denom = red[0]; __syncthreads();
    if (tid < TT) sc[tid] = e / denom;
    __syncthreads();

    // PV: all 256 threads; groups of 64 cover j strided by 4
    {
        int g = tid >> 6, dd = tid & 63;
        const float* vbase = qkv + (size_t)b * TT * (3*EE) + 2*EE + h*DHH + dd;
        float acc = 0.f;
        for (int j = g; j < TT; j += 4) acc = fmaf(sc[j], vbase[(size_t)j * (3*EE)], acc);
        part[g][dd] = acc;
    }
    __syncthreads();
    if (tid < DHH) {
        float o = part[0][tid] + part[1][tid] + part[2][tid] + part[3][tid];
        __nv_bfloat16 hi, lo; split_bf16(o, hi, lo);
        size_t row = (size_t)(b*TT + i);
        int col = h*DHH + tid;
        __nv_bfloat16* op = otri + row * (3*EE);
        op[col] = hi; op[EE + col] = lo; op[2*EE + col] = hi;
    }
}

// ---------------- small fp32 GEMM (head only) ----------------
__global__ void head_gemm_kernel(const float* __restrict__ A, const float* __restrict__ B,
                                 const float* __restrict__ bias, float* __restrict__ C,
                                 int M, int N, int K) {
    const int BN = 64, BK = 16;
    __shared__ float As[BK][8];
    __shared__ float Bs[BK][BN + 1];
    int bn = blockIdx.x * BN;
    int tid = threadIdx.x;
    int tx = tid & 15, ty = tid >> 4;
    float acc[4] = {0.f, 0.f, 0.f, 0.f};  // ty indexes M rows (only 4 valid)
    for (int k0 = 0; k0 < K; k0 += BK) {
        if (tid < BK * M) {
            int m = tid / BK, kk = tid % BK;
            As[kk][m] = A[(size_t)m * K + k0 + kk];
        }
        #pragma unroll
        for (int i = 0; i < 4; i++) {
            int s = tid + i * 256;
            int kk = s >> 6, n = s & 63;
            int gn = bn + n;
            Bs[kk][n] = (gn < N) ? B[(size_t)(k0 + kk) * N + gn] : 0.f;
        }
        __syncthreads();
        if (ty < M) {
            #pragma unroll
            for (int kk = 0; kk < BK; kk++) {
                float a = As[kk][ty];
                #pragma unroll
                for (int j = 0; j < 4; j++)
                    acc[j] = fmaf(a, Bs[kk][tx*4 + j], acc[j]);
            }
        }
        __syncthreads();
    }
    if (ty < M) {
        #pragma unroll
        for (int j = 0; j < 4; j++) {
            int gn = bn + tx*4 + j;
            if (gn < N) C[(size_t)ty * N + gn] = acc[j] + bias[gn];
        }
    }
}

// ---------------- host launcher ----------------
extern "C" void kernel_launch(void* const* d_in, const int* in_sizes, int n_in,
                              void* d_out, int out_size) {
    const float* x         = (const float*)d_in[0];
    const float* conv_w    = (const float*)d_in[1];
    const float* conv_b    = (const float*)d_in[2];
    const float* pos_embed = (const float*)d_in[3];
    const float* cls_token = (const float*)d_in[4];
    const float* ln1_w     = (const float*)d_in[5];
    const float* ln1_b     = (const float*)d_in[6];
    const float* attn_w    = (const float*)d_in[7];
    const float* attn_b    = (const float*)d_in[8];
    const float* proj_w    = (const float*)d_in[9];
    const float* proj_b    = (const float*)d_in[10];
    const float* ln2_w     = (const float*)d_in[11];
    const float* ln2_b     = (const float*)d_in[12];
    const float* fc1_w     = (const float*)d_in[13];
    const float* fc1_b     = (const float*)d_in[14];
    const float* fc2_w     = (const float*)d_in[15];
    const float* fc2_b     = (const float*)d_in[16];
    const float* lnf_w     = (const float*)d_in[17];
    const float* lnf_b     = (const float*)d_in[18];
    const float* head_w    = (const float*)d_in[19];
    const float* head_b    = (const float*)d_in[20];
    float* out = (float*)d_out;

    float *p_h, *p_qkv, *p_tok, *p_cls, *p_part;
    __nv_bfloat16 *p_abf, *p_wbf, *p_lntri;
    cudaGetSymbolAddress((void**)&p_h, g_h);
    cudaGetSymbolAddress((void**)&p_qkv, g_qkv);
    cudaGetSymbolAddress((void**)&p_tok, g_tok);
    cudaGetSymbolAddress((void**)&p_cls, g_cls);
    cudaGetSymbolAddress((void**)&p_part, g_part);
    cudaGetSymbolAddress((void**)&p_abf, g_abf);
    cudaGetSymbolAddress((void**)&p_wbf, g_wbf);
    cudaGetSymbolAddress((void**)&p_lntri, g_lntri);

    // ---- patch embedding ----
    {
        int total = BB*NPAT*KPATCH;
        im2col_tri_kernel<<<(total + 255)/256, 256>>>(x, p_abf);
        int wtot = KPATCH * EE;
        wconv_t_kernel<<<(wtot + 255)/256, 256>>>(conv_w, p_wbf, KPATCH, EE);
        dim3 g(EE/64, (BB*NPAT + 127)/128, 4);
        mma_gemm<0, true, false, false><<<g, 256>>>(
            p_abf, p_wbf, nullptr, nullptr, p_part, nullptr,
            BB*NPAT, EE, 3*KPATCH, (3*KPATCH)/4);
        int mn = BB*NPAT*EE;
        reduce_kernel<false><<<(mn + 255)/256, 256>>>(p_part, 4, conv_b, nullptr, p_tok, mn, EE);
        int th = BB*TT*EE;
        assemble_h_kernel<<<(th + 255)/256, 256>>>(pos_embed, cls_token);
    }

    // ---- transformer layers ----
    for (int l = 0; l < LL; l++) {
        const float* lw1 = ln1_w + (size_t)l * EE;
        const float* lb1 = ln1_b + (size_t)l * EE;
        const float* aw  = attn_w + (size_t)l * EE * 3 * EE;
        const float* ab  = attn_b + (size_t)l * 3 * EE;
        const float* pw  = proj_w + (size_t)l * EE * EE;
        const float* pb  = proj_b + (size_t)l * EE;
        const float* lw2 = ln2_w + (size_t)l * EE;
        const float* lb2 = ln2_b + (size_t)l * EE;
        const float* f1w = fc1_w + (size_t)l * EE * DFF_;
        const float* f1b = fc1_b + (size_t)l * DFF_;
        const float* f2w = fc2_w + (size_t)l * DFF_ * EE;
        const float* f2b = fc2_b + (size_t)l * EE;

        // ln1 -> triple
        ln_tri_kernel<<<MROWS, 256>>>(p_h, lw1, lb1, p_lntri);

        // qkv GEMM: [788,2304] x [2304(=3*768),2304] -> fp32 qkv
        {
            int wtot = EE * 3*EE;
            wconv_std_kernel<<<(wtot + 255)/256, 256>>>(aw, p_wbf, EE, 3*EE);
            dim3 g((3*EE)/64, (MROWS + 127)/128, 1);
            mma_gemm<0, false, false, false><<<g, 256>>>(
                p_lntri, p_wbf, ab, nullptr, p_qkv, nullptr,
                MROWS, 3*EE, 3*EE, 3*EE);
        }

        // attention
        kprep_kernel<<<dim3(BB*NHH, 4), 256>>>(p_qkv);
        attn_kernel<<<BB*NHH*TT, 256>>>(p_qkv, p_abf);

        // proj: split-K=4 partial + reduce(bias, res=h)
        {
            int wtot = EE * EE;
            wconv_std_kernel<<<(wtot + 255)/256, 256>>>(pw, p_wbf, EE, EE);
            dim3 g(EE/64, (MROWS + 127)/128, 4);
            mma_gemm<0, true, false, false><<<g, 256>>>(
                p_abf, p_wbf, nullptr, nullptr, p_part, nullptr,
                MROWS, EE, 3*EE, (3*EE)/4);
            int mn = MROWS*EE;
            reduce_kernel<true><<<(mn + 255)/256, 256>>>(p_part, 4, pb, p_h, p_h, mn, EE);
        }

        // ln2 -> triple
        ln_tri_kernel<<<MROWS, 256>>>(p_h, lw2, lb2, p_lntri);

        // fc1: gelu, triple-out
        {
            int wtot = EE * DFF_;
            wconv_std_kernel<<<(wtot + 255)/256, 256>>>(f1w, p_wbf, EE, DFF_);
            dim3 g(DFF_/64, (MROWS + 127)/128, 1);
            mma_gemm<1, false, false, true><<<g, 256>>>(
                p_lntri, p_wbf, f1b, nullptr, nullptr, p_abf,
                MROWS, DFF_, 3*EE, 3*EE);
        }

        // fc2: split-K=8 partial + reduce(bias, res=h)
        {
            int wtot = DFF_ * EE;
            wconv_std_kernel<<<(wtot + 255)/256, 256>>>(f2w, p_wbf, DFF_, EE);
            dim3 g(EE/64, (MROWS + 127)/128, 8);
            mma_gemm<0, true, false, false><<<g, 256>>>(
                p_abf, p_wbf, nullptr, nullptr, p_part, nullptr,
                MROWS, EE, 3*DFF_, (3*DFF_)/8);
            int mn = MROWS*EE;
            reduce_kernel<true><<<(mn + 255)/256, 256>>>(p_part, 8, f2b, p_h, p_h, mn, EE);
        }
    }

    // ---- final LN (cls rows) + head ----
    ln_kernel<<<BB, 256>>>(p_h, lnf_w, lnf_b, p_cls, EE, (size_t)TT*EE, EE);
    head_gemm_kernel<<<(OUTC + 63)/64, 256>>>(p_cls, head_w, head_b, out, BB, OUTC, EE);
}

// round 5
// speedup vs baseline: 3.2868x; 1.0590x over previous
#include <cuda_runtime.h>
#include <cuda_bf16.h>
#include <math.h>
#include <stdint.h>

// ---------------- problem constants ----------------
#define BB 4
#define CC 3
#define HH 224
#define WW 224
#define PP 16
#define EE 768
#define NHH 12
#define DHH 64
#define LL 2
#define DFF_ 3072
#define OUTC 1000
#define NPAT 196
#define TT 197
#define MROWS (BB*TT)      // 788
#define KPATCH (CC*PP*PP)  // 768

// weight-triple layout offsets (elements)
#define SZ_PATCH_T 1769472      // 3*768*768
#define SZ_QKV_T   5308416      // 3*768*2304
#define SZ_PROJ_T  1769472
#define SZ_FC1_T   7077888      // 3*768*3072
#define SZ_FC2_T   7077888      // 3*3072*768
#define SZ_LAYER_T 21233664
#define OFF_L0     1769472
#define W_TOTAL    44236800

// ---------------- scratch ----------------
__device__ float g_h[MROWS*EE];
__device__ float g_qkv[MROWS*3*EE];
__device__ float g_cls[BB*EE];
__device__ float g_part[8*MROWS*EE];
__device__ __nv_bfloat16 g_abf[MROWS*3*DFF_];   // im2col tri / obuf tri / fc1 tri
__device__ __nv_bfloat16 g_lntri[MROWS*3*EE];
__device__ __nv_bfloat16 g_wall[W_TOTAL];

// ---------------- helpers ----------------
__device__ __forceinline__ uint32_t smaddr(const void* p) {
    return (uint32_t)__cvta_generic_to_shared(p);
}
__device__ __forceinline__ void ldsm_x4(uint32_t& r0, uint32_t& r1, uint32_t& r2, uint32_t& r3, uint32_t a) {
    asm volatile("ldmatrix.sync.aligned.m8n8.x4.shared.b16 {%0,%1,%2,%3}, [%4];"
                 : "=r"(r0), "=r"(r1), "=r"(r2), "=r"(r3) : "r"(a));
}
__device__ __forceinline__ void ldsm_x4_t(uint32_t& r0, uint32_t& r1, uint32_t& r2, uint32_t& r3, uint32_t a) {
    asm volatile("ldmatrix.sync.aligned.m8n8.x4.trans.shared.b16 {%0,%1,%2,%3}, [%4];"
                 : "=r"(r0), "=r"(r1), "=r"(r2), "=r"(r3) : "r"(a));
}
__device__ __forceinline__ void mma_bf16(float* c, uint32_t a0, uint32_t a1, uint32_t a2, uint32_t a3,
                                         uint32_t b0, uint32_t b1) {
    asm volatile("mma.sync.aligned.m16n8k16.row.col.f32.bf16.bf16.f32 "
                 "{%0,%1,%2,%3}, {%4,%5,%6,%7}, {%8,%9}, {%0,%1,%2,%3};"
                 : "+f"(c[0]), "+f"(c[1]), "+f"(c[2]), "+f"(c[3])
                 : "r"(a0), "r"(a1), "r"(a2), "r"(a3), "r"(b0), "r"(b1));
}
__device__ __forceinline__ float gelu_tanh(float v) {
    float v3 = v * v * v;
    return 0.5f * v * (1.0f + tanhf(0.7978845608028654f * (v + 0.044715f * v3)));
}
__device__ __forceinline__ void split_bf16(float v, __nv_bfloat16& hi, __nv_bfloat16& lo) {
    hi = __float2bfloat16(v);
    lo = __float2bfloat16(v - __bfloat162float(hi));
}
__device__ __forceinline__ float block_sum(float v, float* red, int tid) {
    red[tid] = v; __syncthreads();
    for (int st = 128; st > 0; st >>= 1) { if (tid < st) red[tid] += red[tid + st]; __syncthreads(); }
    float r = red[0]; __syncthreads();
    return r;
}

// ---------------- im2col -> bf16 triple ----------------
__global__ void im2col_tri_kernel(const float* __restrict__ x, __nv_bfloat16* __restrict__ out) {
    int idx = blockIdx.x * blockDim.x + threadIdx.x;
    const int total = BB*NPAT*KPATCH;
    if (idx >= total) return;
    int k   = idx % KPATCH;
    int row = idx / KPATCH;
    int b = row / NPAT, t = row % NPAT;
    int ph = t / 14, pw = t % 14;
    int c = k / (PP*PP);
    int r = (k % (PP*PP)) / PP;
    int q = k % PP;
    float v = x[(((size_t)(b*CC + c)*HH) + ph*PP + r) * WW + pw*PP + q];
    __nv_bfloat16 hi, lo; split_bf16(v, hi, lo);
    __nv_bfloat16* o = out + (size_t)row * (3*KPATCH);
    o[k] = hi; o[KPATCH + k] = lo; o[2*KPATCH + k] = hi;
}

// ---------------- one-shot weight conversion (all segments) ----------------
__global__ void wconv_all_kernel(const float* __restrict__ conv_w, const float* __restrict__ attn_w,
                                 const float* __restrict__ proj_w, const float* __restrict__ fc1_w,
                                 const float* __restrict__ fc2_w) {
    const int S_PATCH = 589824;
    const int S_QKV = 1769472, S_PROJ = 589824, S_FC1 = 2359296;
    const int S_LAYER = 7077888;
    const int total = S_PATCH + 2*S_LAYER;
    int idx = blockIdx.x * blockDim.x + threadIdx.x;
    if (idx >= total) return;
    const float* src; __nv_bfloat16* dst; int K, N, rem; bool tr = false;
    if (idx < S_PATCH) {
        rem = idx; src = conv_w; dst = g_wall; K = 768; N = 768; tr = true;
    } else {
        int r = idx - S_PATCH;
        int l = r / S_LAYER; r %= S_LAYER;
        __nv_bfloat16* base = g_wall + OFF_L0 + (size_t)l * SZ_LAYER_T;
        if (r < S_QKV) { src = attn_w + (size_t)l*S_QKV; dst = base; K = 768; N = 2304; rem = r; }
        else if (r < S_QKV + S_PROJ) { src = proj_w + (size_t)l*S_PROJ; dst = base + SZ_QKV_T; K = 768; N = 768; rem = r - S_QKV; }
        else if (r < S_QKV + S_PROJ + S_FC1) { src = fc1_w + (size_t)l*S_FC1; dst = base + SZ_QKV_T + SZ_PROJ_T; K = 768; N = 3072; rem = r - S_QKV - S_PROJ; }
        else { src = fc2_w + (size_t)l*2359296; dst = base + SZ_QKV_T + SZ_PROJ_T + SZ_FC1_T; K = 3072; N = 768; rem = r - S_QKV - S_PROJ - S_FC1; }
    }
    int k = rem / N, n = rem % N;
    float w = tr ? src[(size_t)n*K + k] : src[rem];
    __nv_bfloat16 hi, lo; split_bf16(w, hi, lo);
    dst[(size_t)k*N + n] = hi;
    dst[(size_t)(K + k)*N + n] = hi;
    dst[(size_t)(2*K + k)*N + n] = lo;
}

// ---------------- patch epilogue: reduce + assemble + LN-triple ----------------
__global__ void patch_ln_kernel(const float* __restrict__ part, const float* __restrict__ conv_b,
                                const float* __restrict__ pos_embed, const float* __restrict__ cls_token,
                                const float* __restrict__ lw, const float* __restrict__ lb) {
    int r = blockIdx.x;              // 0..787
    int b = r / TT, t = r % TT;
    int tid = threadIdx.x;
    __shared__ float red[256];
    float v[3];
    #pragma unroll
    for (int p3 = 0; p3 < 3; p3++) {
        int c = tid + p3*256;
        float s;
        if (t == 0) s = cls_token[c];
        else {
            int pr = b*NPAT + (t-1);
            s = conv_b[c] + pos_embed[(size_t)(t-1)*EE + c];
            #pragma unroll
            for (int p = 0; p < 4; p++) s += part[(size_t)p*(BB*NPAT)*EE + (size_t)pr*EE + c];
        }
        g_h[(size_t)r*EE + c] = s;
        v[p3] = s;
    }
    float mu = block_sum(v[0]+v[1]+v[2], red, tid) / EE;
    float sq = 0.f;
    #pragma unroll
    for (int p3 = 0; p3 < 3; p3++) { float d = v[p3]-mu; sq += d*d; }
    float inv = rsqrtf(block_sum(sq, red, tid) / EE + 1e-5f);
    __nv_bfloat16* y = g_lntri + (size_t)r * (3*EE);
    #pragma unroll
    for (int p3 = 0; p3 < 3; p3++) {
        int c = tid + p3*256;
        float o = (v[p3]-mu)*inv*lw[c] + lb[c];
        __nv_bfloat16 hi, lo; split_bf16(o, hi, lo);
        y[c] = hi; y[EE + c] = lo; y[2*EE + c] = hi;
    }
}

// ---------------- fused split-K reduce + bias + residual + optional LN-triple ----------------
template<int S, bool LNOUT>
__global__ void fuse_res_ln_kernel(const float* __restrict__ part, const float* __restrict__ bias,
                                   const float* __restrict__ lw, const float* __restrict__ lb) {
    int r = blockIdx.x;
    int tid = threadIdx.x;
    __shared__ float red[256];
    float v[3];
    #pragma unroll
    for (int p3 = 0; p3 < 3; p3++) {
        int c = tid + p3*256;
        float s = g_h[(size_t)r*EE + c] + bias[c];
        #pragma unroll
        for (int p = 0; p < S; p++) s += part[(size_t)p*MROWS*EE + (size_t)r*EE + c];
        g_h[(size_t)r*EE + c] = s;
        v[p3] = s;
    }
    if (!LNOUT) return;
    float mu = block_sum(v[0]+v[1]+v[2], red, tid) / EE;
    float sq = 0.f;
    #pragma unroll
    for (int p3 = 0; p3 < 3; p3++) { float d = v[p3]-mu; sq += d*d; }
    float inv = rsqrtf(block_sum(sq, red, tid) / EE + 1e-5f);
    __nv_bfloat16* y = g_lntri + (size_t)r * (3*EE);
    #pragma unroll
    for (int p3 = 0; p3 < 3; p3++) {
        int c = tid + p3*256;
        float o = (v[p3]-mu)*inv*lw[c] + lb[c];
        __nv_bfloat16 hi, lo; split_bf16(o, hi, lo);
        y[c] = hi; y[EE + c] = lo; y[2*EE + c] = hi;
    }
}

// ---------------- final LN (cls rows, fp32 out) ----------------
__global__ void ln_kernel(const float* __restrict__ in, const float* __restrict__ w,
                          const float* __restrict__ bch, float* __restrict__ out,
                          int cols, size_t in_stride, size_t out_stride) {
    int row = blockIdx.x;
    const float* x = in + (size_t)row * in_stride;
    float* y = out + (size_t)row * out_stride;
    __shared__ float red[256];
    int tid = threadIdx.x;
    float s = 0.f;
    for (int c = tid; c < cols; c += 256) s += x[c];
    float mu = block_sum(s, red, tid) / cols;
    float s2 = 0.f;
    for (int c = tid; c < cols; c += 256) { float d = x[c]-mu; s2 += d*d; }
    float inv = rsqrtf(block_sum(s2, red, tid) / cols + 1e-5f);
    for (int c = tid; c < cols; c += 256)
        y[c] = (x[c]-mu)*inv*w[c] + bch[c];
}

// ================= bf16 tensor-core GEMM (mma.sync m16n8k16) =================
template<int ACT, bool PARTIAL, bool TRIPLE>
__global__ __launch_bounds__(256)
void mma_gemm(const __nv_bfloat16* __restrict__ A, const __nv_bfloat16* __restrict__ B,
              const float* __restrict__ bias,
              float* __restrict__ C, __nv_bfloat16* __restrict__ Ctri,
              int M, int N, int Ka, int klen) {
    __shared__ __nv_bfloat16 As[2][128*40];
    __shared__ __nv_bfloat16 Bs[2][32*72];

    int bn = blockIdx.x * 64;
    int bm = blockIdx.y * 128;
    int kz = blockIdx.z * klen;
    int tid = threadIdx.x;
    int lane = tid & 31;
    int w = tid >> 5;
    int wm = (w & 3) * 32;
    int wn = (w >> 2) * 32;

    int ar0 = tid >> 2;
    int ar1 = ar0 + 64;
    int as0 = (tid & 3) * 8;
    int brow = tid >> 3;
    int bseg = (tid & 7) * 8;

    float acc[2][4][4];
    #pragma unroll
    for (int i = 0; i < 2; i++)
        #pragma unroll
        for (int j = 0; j < 4; j++)
            #pragma unroll
            for (int k = 0; k < 4; k++) acc[i][j][k] = 0.f;

    uint4 ra0, ra1, rb;
    const uint4 zero4 = make_uint4(0, 0, 0, 0);

    auto fetch = [&](int kt) {
        int k0 = kz + kt * 32;
        int gm0 = bm + ar0, gm1 = bm + ar1;
        ra0 = (gm0 < M) ? *(const uint4*)(A + (size_t)gm0 * Ka + k0 + as0) : zero4;
        ra1 = (gm1 < M) ? *(const uint4*)(A + (size_t)gm1 * Ka + k0 + as0) : zero4;
        rb  = *(const uint4*)(B + (size_t)(k0 + brow) * N + bn + bseg);
    };
    auto stash = [&](int b) {
        *(uint4*)&As[b][ar0*40 + as0] = ra0;
        *(uint4*)&As[b][ar1*40 + as0] = ra1;
        *(uint4*)&Bs[b][brow*72 + bseg] = rb;
    };

    fetch(0); stash(0); __syncthreads();
    int nk = klen >> 5;
    int buf = 0;
    for (int kt = 0; kt < nk; kt++) {
        if (kt + 1 < nk) fetch(kt + 1);
        #pragma unroll
        for (int s = 0; s < 2; s++) {
            uint32_t a[2][4], bf[4][2];
            #pragma unroll
            for (int mt = 0; mt < 2; mt++) {
                uint32_t ad = smaddr(&As[buf][(wm + mt*16 + (lane & 15))*40 + s*16 + (lane >> 4)*8]);
                ldsm_x4(a[mt][0], a[mt][1], a[mt][2], a[mt][3], ad);
            }
            #pragma unroll
            for (int h2 = 0; h2 < 2; h2++) {
                uint32_t ad = smaddr(&Bs[buf][(s*16 + (lane & 15))*72 + wn + h2*16 + (lane >> 4)*8]);
                ldsm_x4_t(bf[h2*2][0], bf[h2*2][1], bf[h2*2+1][0], bf[h2*2+1][1], ad);
            }
            #pragma unroll
            for (int mt = 0; mt < 2; mt++)
                #pragma unroll
                for (int nt = 0; nt < 4; nt++)
                    mma_bf16(acc[mt][nt], a[mt][0], a[mt][1], a[mt][2], a[mt][3],
                             bf[nt][0], bf[nt][1]);
        }
        if (kt + 1 < nk) { buf ^= 1; stash(buf); __syncthreads(); }
    }

    #pragma unroll
    for (int mt = 0; mt < 2; mt++) {
        int rbase = bm + wm + mt*16 + (lane >> 2);
        #pragma unroll
        for (int nt = 0; nt < 4; nt++) {
            int cbase = bn + wn + nt*8 + (lane & 3)*2;
            #pragma unroll
            for (int half = 0; half < 2; half++) {
                int gm = rbase + half*8;
                if (gm >= M) continue;
                #pragma unroll
                for (int e = 0; e < 2; e++) {
                    int gn = cbase + e;
                    float v = acc[mt][nt][half*2 + e];
                    if (PARTIAL) {
                        C[(size_t)blockIdx.z * M * N + (size_t)gm * N + gn] = v;
                    } else {
                        v += bias[gn];
                        if (ACT == 1) v = gelu_tanh(v);
                        if (TRIPLE) {
                            __nv_bfloat16 hi, lo; split_bf16(v, hi, lo);
                            __nv_bfloat16* o = Ctri + (size_t)gm * (3*N);
                            o[gn] = hi; o[N + gn] = lo; o[2*N + gn] = hi;
                        } else {
                            C[(size_t)gm * N + gn] = v;
                        }
                    }
                }
            }
        }
    }
}

// ---------------- flash-style Tversky attention ----------------
// score(i,j) = 2*sum_d min(q+,k+) / (qs+ks+2eps); softmax (no max-sub; s in [0,1]); o = P V.
// block = (itile, h, b). 64 i-rows per block, j in chunks of 32.
__global__ __launch_bounds__(256)
void attn_flash_kernel(const float* __restrict__ qkv, __nv_bfloat16* __restrict__ otri) {
    int it = blockIdx.x, h = blockIdx.y, b = blockIdx.z;
    int i0 = it * 64;
    __shared__ float Qs[64][68];    // [d][i]
    __shared__ float Ks[64][36];    // [d][j]
    __shared__ float Vs[32][68];    // [j][d]
    __shared__ float Ps[64][36];    // [i][j]
    __shared__ float qs_s[64], ks_s[32], den[64];
    int tid = threadIdx.x;

    // load Q tile (relu, transposed): 64 i x 64 d = 1024 float4 -> p < 4
    #pragma unroll
    for (int p = 0; p < 4; p++) {
        int idx = tid + p*256;
        int i = idx >> 4, d4 = (idx & 15) * 4;
        int gi = i0 + i;
        float4 q = make_float4(0.f,0.f,0.f,0.f);
        if (gi < TT) q = *(const float4*)(qkv + (size_t)(b*TT + gi)*(3*EE) + h*DHH + d4);
        Qs[d4+0][i] = fmaxf(q.x, 0.f);
        Qs[d4+1][i] = fmaxf(q.y, 0.f);
        Qs[d4+2][i] = fmaxf(q.z, 0.f);
        Qs[d4+3][i] = fmaxf(q.w, 0.f);
    }
    if (tid < 64) den[tid] = 0.f;
    __syncthreads();
    if (tid < 64) {
        float s = 0.f;
        #pragma unroll
        for (int d = 0; d < 64; d++) s += Qs[d][tid];
        qs_s[tid] = s;
    }

    float o[4][4];
    #pragma unroll
    for (int r = 0; r < 4; r++)
        #pragma unroll
        for (int c = 0; c < 4; c++) o[r][c] = 0.f;

    int tj = tid & 15, ti = tid >> 4;   // scores: i = ti*4+r, j = tj*2+e

    for (int jc = 0; jc < 7; jc++) {
        int j0 = jc * 32;
        __syncthreads();
        // load K (relu, transposed) + V chunk: 32 j x 16 chunks = 512 float4 -> p < 2
        #pragma unroll
        for (int p = 0; p < 2; p++) {
            int idx = tid + p*256;
            int j = idx >> 4, d4 = (idx & 15) * 4;
            int gj = j0 + j;
            float4 kv = make_float4(0.f,0.f,0.f,0.f);
            float4 vv = make_float4(0.f,0.f,0.f,0.f);
            if (gj < TT) {
                const float* rowp = qkv + (size_t)(b*TT + gj)*(3*EE) + h*DHH;
                kv = *(const float4*)(rowp + EE + d4);
                vv = *(const float4*)(rowp + 2*EE + d4);
            }
            Ks[d4+0][j] = fmaxf(kv.x, 0.f);
            Ks[d4+1][j] = fmaxf(kv.y, 0.f);
            Ks[d4+2][j] = fmaxf(kv.z, 0.f);
            Ks[d4+3][j] = fmaxf(kv.w, 0.f);
            *(float4*)&Vs[j][d4] = vv;
        }
        __syncthreads();
        if (tid < 32) {
            float s = 0.f;
            #pragma unroll
            for (int d = 0; d < 64; d++) s += Ks[d][tid];
            ks_s[tid] = s;
        }
        __syncthreads();

        // scores: sum of min
        float m[4][2];
        #pragma unroll
        for (int r = 0; r < 4; r++) { m[r][0] = 0.f; m[r][1] = 0.f; }
        #pragma unroll 8
        for (int d = 0; d < 64; d++) {
            float4 qv = *(const float4*)&Qs[d][ti*4];
            float2 kv = *(const float2*)&Ks[d][tj*2];
            m[0][0] += fminf(qv.x, kv.x); m[0][1] += fminf(qv.x, kv.y);
            m[1][0] += fminf(qv.y, kv.x); m[1][1] += fminf(qv.y, kv.y);
            m[2][0] += fminf(qv.z, kv.x); m[2][1] += fminf(qv.z, kv.y);
            m[3][0] += fminf(qv.w, kv.x); m[3][1] += fminf(qv.w, kv.y);
        }
        #pragma unroll
        for (int r = 0; r < 4; r++) {
            int i = ti*4 + r;
            int gi = i0 + i;
            #pragma unroll
            for (int e = 0; e < 2; e++) {
                int j = tj*2 + e;
                int gj = j0 + j;
                float sc = 2.f * m[r][e] / (qs_s[i] + ks_s[j] + 2e-8f);
                Ps[i][j] = (gi < TT && gj < TT) ? expf(sc) : 0.f;
            }
        }
        __syncthreads();
        if (tid < 64) {
            float s = 0.f;
            #pragma unroll
            for (int j = 0; j < 32; j++) s += Ps[tid][j];
            den[tid] += s;
        }
        // PV accumulate
        #pragma unroll 4
        for (int jj = 0; jj < 32; jj++) {
            float4 vv = *(const float4*)&Vs[jj][tj*4];
            #pragma unroll
            for (int r = 0; r < 4; r++) {
                float pw = Ps[ti*4 + r][jj];
                o[r][0] += pw * vv.x;
                o[r][1] += pw * vv.y;
                o[r][2] += pw * vv.z;
                o[r][3] += pw * vv.w;
            }
        }
    }
    __syncthreads();

    #pragma unroll
    for (int r = 0; r < 4; r++) {
        int i = ti*4 + r;
        int gi = i0 + i;
        if (gi >= TT) continue;
        float dn = den[i];
        __nv_bfloat16* op = otri + (size_t)(b*TT + gi) * (3*EE);
        #pragma unroll
        for (int c = 0; c < 4; c++) {
            float val = o[r][c] / dn;
            int col = h*DHH + tj*4 + c;
            __nv_bfloat16 hi, lo; split_bf16(val, hi, lo);
            op[col] = hi; op[EE + col] = lo; op[2*EE + col] = hi;
        }
    }
}

// ---------------- small fp32 GEMM (head only) ----------------
__global__ void head_gemm_kernel(const float* __restrict__ A, const float* __restrict__ B,
                                 const float* __restrict__ bias, float* __restrict__ C,
                                 int M, int N, int K) {
    const int BN = 64, BK = 16;
    __shared__ float As[BK][8];
    __shared__ float Bs[BK][BN + 1];
    int bn = blockIdx.x * BN;
    int tid = threadIdx.x;
    int tx = tid & 15, ty = tid >> 4;
    float acc[4] = {0.f, 0.f, 0.f, 0.f};
    for (int k0 = 0; k0 < K; k0 += BK) {
        if (tid < BK * M) {
            int m = tid / BK, kk = tid % BK;
            As[kk][m] = A[(size_t)m * K + k0 + kk];
        }
        #pragma unroll
        for (int i = 0; i < 4; i++) {
            int s = tid + i * 256;
            int kk = s >> 6, n = s & 63;
            int gn = bn + n;
            Bs[kk][n] = (gn < N) ? B[(size_t)(k0 + kk) * N + gn] : 0.f;
        }
        __syncthreads();
        if (ty < M) {
            #pragma unroll
            for (int kk = 0; kk < BK; kk++) {
                float a = As[kk][ty];
                #pragma unroll
                for (int j = 0; j < 4; j++)
                    acc[j] = fmaf(a, Bs[kk][tx*4 + j], acc[j]);
            }
        }
        __syncthreads();
    }
    if (ty < M) {
        #pragma unroll
        for (int j = 0; j < 4; j++) {
            int gn = bn + tx*4 + j;
            if (gn < N) C[(size_t)ty * N + gn] = acc[j] + bias[gn];
        }
    }
}

// ---------------- host launcher ----------------
extern "C" void kernel_launch(void* const* d_in, const int* in_sizes, int n_in,
                              void* d_out, int out_size) {
    const float* x         = (const float*)d_in[0];
    const float* conv_w    = (const float*)d_in[1];
    const float* conv_b    = (const float*)d_in[2];
    const float* pos_embed = (const float*)d_in[3];
    const float* cls_token = (const float*)d_in[4];
    const float* ln1_w     = (const float*)d_in[5];
    const float* ln1_b     = (const float*)d_in[6];
    const float* attn_w    = (const float*)d_in[7];
    const float* attn_b    = (const float*)d_in[8];
    const float* proj_w    = (const float*)d_in[9];
    const float* proj_b    = (const float*)d_in[10];
    const float* ln2_w     = (const float*)d_in[11];
    const float* ln2_b     = (const float*)d_in[12];
    const float* fc1_w     = (const float*)d_in[13];
    const float* fc1_b     = (const float*)d_in[14];
    const float* fc2_w     = (const float*)d_in[15];
    const float* fc2_b     = (const float*)d_in[16];
    const float* lnf_w     = (const float*)d_in[17];
    const float* lnf_b     = (const float*)d_in[18];
    const float* head_w    = (const float*)d_in[19];
    const float* head_b    = (const float*)d_in[20];
    float* out = (float*)d_out;

    float *p_h, *p_qkv, *p_cls, *p_part;
    __nv_bfloat16 *p_abf, *p_lntri, *p_wall;
    cudaGetSymbolAddress((void**)&p_h, g_h);
    cudaGetSymbolAddress((void**)&p_qkv, g_qkv);
    cudaGetSymbolAddress((void**)&p_cls, g_cls);
    cudaGetSymbolAddress((void**)&p_part, g_part);
    cudaGetSymbolAddress((void**)&p_abf, g_abf);
    cudaGetSymbolAddress((void**)&p_lntri, g_lntri);
    cudaGetSymbolAddress((void**)&p_wall, g_wall);

    // weight pointers in triple buffer
    const __nv_bfloat16* wPatch = p_wall;
    const __nv_bfloat16* wQKV[LL], *wProj[LL], *wFc1[LL], *wFc2[LL];
    for (int l = 0; l < LL; l++) {
        const __nv_bfloat16* base = p_wall + OFF_L0 + (size_t)l * SZ_LAYER_T;
        wQKV[l] = base;
        wProj[l] = base + SZ_QKV_T;
        wFc1[l] = base + SZ_QKV_T + SZ_PROJ_T;
        wFc2[l] = base + SZ_QKV_T + SZ_PROJ_T + SZ_FC1_T;
    }

    // ---- prep ----
    {
        int total = BB*NPAT*KPATCH;
        im2col_tri_kernel<<<(total + 255)/256, 256>>>(x, p_abf);
        int wtot = 589824 + 2*7077888;
        wconv_all_kernel<<<(wtot + 255)/256, 256>>>(conv_w, attn_w, proj_w, fc1_w, fc2_w);
    }

    // ---- patch embedding GEMM + fused epilogue/LN ----
    {
        dim3 g(EE/64, (BB*NPAT + 127)/128, 4);
        mma_gemm<0, true, false><<<g, 256>>>(
            p_abf, wPatch, nullptr, p_part, nullptr, BB*NPAT, EE, 3*KPATCH, (3*KPATCH)/4);
        patch_ln_kernel<<<MROWS, 256>>>(p_part, conv_b, pos_embed, cls_token, ln1_w, ln1_b);
    }

    // ---- transformer layers ----
    for (int l = 0; l < LL; l++) {
        const float* ab  = attn_b + (size_t)l * 3 * EE;
        const float* pb  = proj_b + (size_t)l * EE;
        const float* lw2 = ln2_w + (size_t)l * EE;
        const float* lb2 = ln2_b + (size_t)l * EE;
        const float* f1b = fc1_b + (size_t)l * DFF_;
        const float* f2b = fc2_b + (size_t)l * EE;

        // qkv
        {
            dim3 g((3*EE)/64, (MROWS + 127)/128, 1);
            mma_gemm<0, false, false><<<g, 256>>>(
                p_lntri, wQKV[l], ab, p_qkv, nullptr, MROWS, 3*EE, 3*EE, 3*EE);
        }
        // attention -> otri in g_abf
        attn_flash_kernel<<<dim3(4, NHH, BB), 256>>>(p_qkv, p_abf);
        // proj split-4 + fused reduce/res/LN2
        {
            dim3 g(EE/64, (MROWS + 127)/128, 4);
            mma_gemm<0, true, false><<<g, 256>>>(
                p_abf, wProj[l], nullptr, p_part, nullptr, MROWS, EE, 3*EE, (3*EE)/4);
            fuse_res_ln_kernel<4, true><<<MROWS, 256>>>(p_part, pb, lw2, lb2);
        }
        // fc1 (gelu, triple out)
        {
            dim3 g(DFF_/64, (MROWS + 127)/128, 1);
            mma_gemm<1, false, true><<<g, 256>>>(
                p_lntri, wFc1[l], f1b, nullptr, p_abf, MROWS, DFF_, 3*EE, 3*EE);
        }
        // fc2 split-8 + fused reduce/res (+ LN1 of next layer)
        {
            dim3 g(EE/64, (MROWS + 127)/128, 8);
            mma_gemm<0, true, false><<<g, 256>>>(
                p_abf, wFc2[l], nullptr, p_part, nullptr, MROWS, EE, 3*DFF_, (3*DFF_)/8);
            if (l + 1 < LL) {
                fuse_res_ln_kernel<8, true><<<MROWS, 256>>>(
                    p_part, f2b, ln1_w + (size_t)(l+1)*EE, ln1_b + (size_t)(l+1)*EE);
            } else {
                fuse_res_ln_kernel<8, false><<<MROWS, 256>>>(p_part, f2b, nullptr, nullptr);
            }
        }
    }

    // ---- final LN (cls rows) + head ----
    ln_kernel<<<BB, 256>>>(p_h, lnf_w, lnf_b, p_cls, EE, (size_t)TT*EE, EE);
    head_gemm_kernel<<<(OUTC + 63)/64, 256>>>(p_cls, head_w, head_b, out, BB, OUTC, EE);
}

// round 6
// speedup vs baseline: 3.5633x; 1.0841x over previous
#include <cuda_runtime.h>
#include <cuda_bf16.h>
#include <math.h>
#include <stdint.h>

// ---------------- problem constants ----------------
#define BB 4
#define CC 3
#define HH 224
#define WW 224
#define PP 16
#define EE 768
#define NHH 12
#define DHH 64
#define LL 2
#define DFF_ 3072
#define OUTC 1000
#define NPAT 196
#define TT 197
#define MROWS (BB*TT)      // 788
#define KPATCH (CC*PP*PP)  // 768

// dual-weight layout (elements): [W_hi (K rows); W_lo (K rows)] x N
#define SZ_PATCH_D 1179648      // 2*768*768
#define SZ_QKV_D   3538944      // 2*768*2304
#define SZ_PROJ_D  1179648
#define SZ_FC1_D   4718592      // 2*768*3072
#define SZ_FC2_D   4718592      // 2*3072*768
#define SZ_LAYER_D 14155776
#define OFF_L0     1179648
#define W_TOTAL    29491200

// ---------------- scratch ----------------
__device__ float g_h[MROWS*EE];
__device__ float g_qkv[MROWS*3*EE];
__device__ float g_cls[BB*EE];
__device__ float g_part[4*MROWS*EE];
__device__ __nv_bfloat16 g_abf[MROWS*2*DFF_];   // im2col dual / attn-out dual / fc1-out dual
__device__ __nv_bfloat16 g_lntri[MROWS*2*EE];   // LN dual
__device__ __nv_bfloat16 g_wall[W_TOTAL];

// ---------------- helpers ----------------
__device__ __forceinline__ uint32_t smaddr(const void* p) {
    return (uint32_t)__cvta_generic_to_shared(p);
}
__device__ __forceinline__ void ldsm_x4(uint32_t& r0, uint32_t& r1, uint32_t& r2, uint32_t& r3, uint32_t a) {
    asm volatile("ldmatrix.sync.aligned.m8n8.x4.shared.b16 {%0,%1,%2,%3}, [%4];"
                 : "=r"(r0), "=r"(r1), "=r"(r2), "=r"(r3) : "r"(a));
}
__device__ __forceinline__ void ldsm_x4_t(uint32_t& r0, uint32_t& r1, uint32_t& r2, uint32_t& r3, uint32_t a) {
    asm volatile("ldmatrix.sync.aligned.m8n8.x4.trans.shared.b16 {%0,%1,%2,%3}, [%4];"
                 : "=r"(r0), "=r"(r1), "=r"(r2), "=r"(r3) : "r"(a));
}
__device__ __forceinline__ void mma_bf16(float* c, uint32_t a0, uint32_t a1, uint32_t a2, uint32_t a3,
                                         uint32_t b0, uint32_t b1) {
    asm volatile("mma.sync.aligned.m16n8k16.row.col.f32.bf16.bf16.f32 "
                 "{%0,%1,%2,%3}, {%4,%5,%6,%7}, {%8,%9}, {%0,%1,%2,%3};"
                 : "+f"(c[0]), "+f"(c[1]), "+f"(c[2]), "+f"(c[3])
                 : "r"(a0), "r"(a1), "r"(a2), "r"(a3), "r"(b0), "r"(b1));
}
__device__ __forceinline__ float gelu_tanh(float v) {
    float v3 = v * v * v;
    return 0.5f * v * (1.0f + tanhf(0.7978845608028654f * (v + 0.044715f * v3)));
}
__device__ __forceinline__ void split_bf16(float v, __nv_bfloat16& hi, __nv_bfloat16& lo) {
    hi = __float2bfloat16(v);
    lo = __float2bfloat16(v - __bfloat162float(hi));
}
__device__ __forceinline__ float block_sum(float v, float* red, int tid) {
    red[tid] = v; __syncthreads();
    for (int st = 128; st > 0; st >>= 1) { if (tid < st) red[tid] += red[tid + st]; __syncthreads(); }
    float r = red[0]; __syncthreads();
    return r;
}

// ---------------- im2col -> bf16 dual [784, 2*768] ----------------
__global__ void im2col_dual_kernel(const float* __restrict__ x, __nv_bfloat16* __restrict__ out) {
    int idx = blockIdx.x * blockDim.x + threadIdx.x;
    const int total = BB*NPAT*KPATCH;
    if (idx >= total) return;
    int k   = idx % KPATCH;
    int row = idx / KPATCH;
    int b = row / NPAT, t = row % NPAT;
    int ph = t / 14, pw = t % 14;
    int c = k / (PP*PP);
    int r = (k % (PP*PP)) / PP;
    int q = k % PP;
    float v = x[(((size_t)(b*CC + c)*HH) + ph*PP + r) * WW + pw*PP + q];
    __nv_bfloat16 hi, lo; split_bf16(v, hi, lo);
    __nv_bfloat16* o = out + (size_t)row * (2*KPATCH);
    o[k] = hi; o[KPATCH + k] = lo;
}

// ---------------- one-shot dual weight conversion ----------------
__global__ void wconv_all_kernel(const float* __restrict__ conv_w, const float* __restrict__ attn_w,
                                 const float* __restrict__ proj_w, const float* __restrict__ fc1_w,
                                 const float* __restrict__ fc2_w) {
    const int S_PATCH = 589824;
    const int S_QKV = 1769472, S_PROJ = 589824, S_FC1 = 2359296;
    const int S_LAYER = 7077888;
    const int total = S_PATCH + 2*S_LAYER;
    int idx = blockIdx.x * blockDim.x + threadIdx.x;
    if (idx >= total) return;
    const float* src; __nv_bfloat16* dst; int K, N, rem; bool tr = false;
    if (idx < S_PATCH) {
        rem = idx; src = conv_w; dst = g_wall; K = 768; N = 768; tr = true;
    } else {
        int r = idx - S_PATCH;
        int l = r / S_LAYER; r %= S_LAYER;
        __nv_bfloat16* base = g_wall + OFF_L0 + (size_t)l * SZ_LAYER_D;
        if (r < S_QKV) { src = attn_w + (size_t)l*S_QKV; dst = base; K = 768; N = 2304; rem = r; }
        else if (r < S_QKV + S_PROJ) { src = proj_w + (size_t)l*S_PROJ; dst = base + SZ_QKV_D; K = 768; N = 768; rem = r - S_QKV; }
        else if (r < S_QKV + S_PROJ + S_FC1) { src = fc1_w + (size_t)l*S_FC1; dst = base + SZ_QKV_D + SZ_PROJ_D; K = 768; N = 3072; rem = r - S_QKV - S_PROJ; }
        else { src = fc2_w + (size_t)l*2359296; dst = base + SZ_QKV_D + SZ_PROJ_D + SZ_FC1_D; K = 3072; N = 768; rem = r - S_QKV - S_PROJ - S_FC1; }
    }
    int k = rem / N, n = rem % N;
    float w = tr ? src[(size_t)n*K + k] : src[rem];
    __nv_bfloat16 hi, lo; split_bf16(w, hi, lo);
    dst[(size_t)k*N + n] = hi;
    dst[(size_t)(K + k)*N + n] = lo;
}

// ---------------- patch epilogue: reduce + assemble + LN-dual ----------------
__global__ void patch_ln_kernel(const float* __restrict__ part, const float* __restrict__ conv_b,
                                const float* __restrict__ pos_embed, const float* __restrict__ cls_token,
                                const float* __restrict__ lw, const float* __restrict__ lb) {
    int r = blockIdx.x;
    int b = r / TT, t = r % TT;
    int tid = threadIdx.x;
    __shared__ float red[256];
    float v[3];
    #pragma unroll
    for (int p3 = 0; p3 < 3; p3++) {
        int c = tid + p3*256;
        float s;
        if (t == 0) s = cls_token[c];
        else {
            int pr = b*NPAT + (t-1);
            s = conv_b[c] + pos_embed[(size_t)(t-1)*EE + c];
            #pragma unroll
            for (int p = 0; p < 4; p++) s += part[(size_t)p*(BB*NPAT)*EE + (size_t)pr*EE + c];
        }
        g_h[(size_t)r*EE + c] = s;
        v[p3] = s;
    }
    float mu = block_sum(v[0]+v[1]+v[2], red, tid) / EE;
    float sq = 0.f;
    #pragma unroll
    for (int p3 = 0; p3 < 3; p3++) { float d = v[p3]-mu; sq += d*d; }
    float inv = rsqrtf(block_sum(sq, red, tid) / EE + 1e-5f);
    __nv_bfloat16* y = g_lntri + (size_t)r * (2*EE);
    #pragma unroll
    for (int p3 = 0; p3 < 3; p3++) {
        int c = tid + p3*256;
        float o = (v[p3]-mu)*inv*lw[c] + lb[c];
        __nv_bfloat16 hi, lo; split_bf16(o, hi, lo);
        y[c] = hi; y[EE + c] = lo;
    }
}

// ---------------- fused split-K reduce + bias + residual + optional LN-dual ----------------
template<int S, bool LNOUT>
__global__ void fuse_res_ln_kernel(const float* __restrict__ part, const float* __restrict__ bias,
                                   const float* __restrict__ lw, const float* __restrict__ lb) {
    int r = blockIdx.x;
    int tid = threadIdx.x;
    __shared__ float red[256];
    float v[3];
    #pragma unroll
    for (int p3 = 0; p3 < 3; p3++) {
        int c = tid + p3*256;
        float s = g_h[(size_t)r*EE + c] + bias[c];
        #pragma unroll
        for (int p = 0; p < S; p++) s += part[(size_t)p*MROWS*EE + (size_t)r*EE + c];
        g_h[(size_t)r*EE + c] = s;
        v[p3] = s;
    }
    if (!LNOUT) return;
    float mu = block_sum(v[0]+v[1]+v[2], red, tid) / EE;
    float sq = 0.f;
    #pragma unroll
    for (int p3 = 0; p3 < 3; p3++) { float d = v[p3]-mu; sq += d*d; }
    float inv = rsqrtf(block_sum(sq, red, tid) / EE + 1e-5f);
    __nv_bfloat16* y = g_lntri + (size_t)r * (2*EE);
    #pragma unroll
    for (int p3 = 0; p3 < 3; p3++) {
        int c = tid + p3*256;
        float o = (v[p3]-mu)*inv*lw[c] + lb[c];
        __nv_bfloat16 hi, lo; split_bf16(o, hi, lo);
        y[c] = hi; y[EE + c] = lo;
    }
}

// ---------------- final LN (cls rows, fp32 out) ----------------
__global__ void ln_kernel(const float* __restrict__ in, const float* __restrict__ w,
                          const float* __restrict__ bch, float* __restrict__ out,
                          int cols, size_t in_stride, size_t out_stride) {
    int row = blockIdx.x;
    const float* x = in + (size_t)row * in_stride;
    float* y = out + (size_t)row * out_stride;
    __shared__ float red[256];
    int tid = threadIdx.x;
    float s = 0.f;
    for (int c = tid; c < cols; c += 256) s += x[c];
    float mu = block_sum(s, red, tid) / cols;
    float s2 = 0.f;
    for (int c = tid; c < cols; c += 256) { float d = x[c]-mu; s2 += d*d; }
    float inv = rsqrtf(block_sum(s2, red, tid) / cols + 1e-5f);
    for (int c = tid; c < cols; c += 256)
        y[c] = (x[c]-mu)*inv*w[c] + bch[c];
}

// ================= bf16 mma GEMM, 128x128x32, dual-segment mapping =================
// Logical K = 3*Kseg: A' = [Ahi, Alo, Ahi] stored as [hi|lo] (width 2*Kseg);
// B' = [Bhi; Bhi; Blo] stored as [Bhi; Blo] (2*Kseg rows).
// grid = (N/128, ceil(M/128), S); klen = logical K chunk (mult of 32).
template<int ACT, bool PARTIAL, bool DUAL>
__global__ __launch_bounds__(256, 2)
void mma_gemm(const __nv_bfloat16* __restrict__ A, const __nv_bfloat16* __restrict__ B,
              const float* __restrict__ bias,
              float* __restrict__ C, __nv_bfloat16* __restrict__ Cd,
              int M, int N, int Kseg, int klen) {
    __shared__ __nv_bfloat16 As[2][128*40];   // [row][k] pad to 40
    __shared__ __nv_bfloat16 Bs[2][32*136];   // [k][n] pad to 136

    int bn = blockIdx.x * 128;
    int bm = blockIdx.y * 128;
    int kz = blockIdx.z * klen;
    int Wa = 2 * Kseg;
    int tid = threadIdx.x;
    int lane = tid & 31;
    int w = tid >> 5;
    int wm = (w & 3) * 32;     // 4 m-warps
    int wn = (w >> 2) * 64;    // 2 n-warps

    int arow = tid >> 2;           // 0..63 (+64 for p=1)
    int acs  = (tid & 3) * 8;
    int brow = tid >> 4;           // 0..15 (+16 for p=1)
    int bcs  = (tid & 15) * 8;

    float acc[2][8][4];
    #pragma unroll
    for (int i = 0; i < 2; i++)
        #pragma unroll
        for (int j = 0; j < 8; j++)
            #pragma unroll
            for (int k = 0; k < 4; k++) acc[i][j][k] = 0.f;

    uint4 ra[2], rb[2];
    const uint4 zero4 = make_uint4(0, 0, 0, 0);

    auto fetch = [&](int kt) {
        int k0 = kz + kt * 32;
        int ka0 = (k0 < Wa) ? k0 : k0 - Wa;        // A: third segment -> hi again
        int kb0 = (k0 < Kseg) ? k0 : k0 - Kseg;    // B: second segment -> hi rows
        #pragma unroll
        for (int p = 0; p < 2; p++) {
            int gm = bm + arow + p * 64;
            ra[p] = (gm < M) ? *(const uint4*)(A + (size_t)gm * Wa + ka0 + acs) : zero4;
            rb[p] = *(const uint4*)(B + (size_t)(kb0 + brow + p * 16) * N + bn + bcs);
        }
    };
    auto stash = [&](int b) {
        #pragma unroll
        for (int p = 0; p < 2; p++) {
            *(uint4*)&As[b][(arow + p * 64) * 40 + acs] = ra[p];
            *(uint4*)&Bs[b][(brow + p * 16) * 136 + bcs] = rb[p];
        }
    };

    fetch(0); stash(0); __syncthreads();
    int nk = klen >> 5;
    int buf = 0;
    for (int kt = 0; kt < nk; kt++) {
        if (kt + 1 < nk) fetch(kt + 1);
        #pragma unroll
        for (int s = 0; s < 2; s++) {
            uint32_t a[2][4], bf[8][2];
            #pragma unroll
            for (int mt = 0; mt < 2; mt++) {
                uint32_t ad = smaddr(&As[buf][(wm + mt*16 + (lane & 15))*40 + s*16 + (lane >> 4)*8]);
                ldsm_x4(a[mt][0], a[mt][1], a[mt][2], a[mt][3], ad);
            }
            #pragma unroll
            for (int h2 = 0; h2 < 4; h2++) {
                uint32_t ad = smaddr(&Bs[buf][(s*16 + (lane & 15))*136 + wn + h2*16 + (lane >> 4)*8]);
                ldsm_x4_t(bf[h2*2][0], bf[h2*2][1], bf[h2*2+1][0], bf[h2*2+1][1], ad);
            }
            #pragma unroll
            for (int mt = 0; mt < 2; mt++)
                #pragma unroll
                for (int nt = 0; nt < 8; nt++)
                    mma_bf16(acc[mt][nt], a[mt][0], a[mt][1], a[mt][2], a[mt][3],
                             bf[nt][0], bf[nt][1]);
        }
        if (kt + 1 < nk) { buf ^= 1; stash(buf); __syncthreads(); }
    }

    #pragma unroll
    for (int mt = 0; mt < 2; mt++) {
        int rbase = bm + wm + mt*16 + (lane >> 2);
        #pragma unroll
        for (int nt = 0; nt < 8; nt++) {
            int cbase = bn + wn + nt*8 + (lane & 3)*2;
            #pragma unroll
            for (int half = 0; half < 2; half++) {
                int gm = rbase + half*8;
                if (gm >= M) continue;
                #pragma unroll
                for (int e = 0; e < 2; e++) {
                    int gn = cbase + e;
                    float v = acc[mt][nt][half*2 + e];
                    if (PARTIAL) {
                        C[(size_t)blockIdx.z * M * N + (size_t)gm * N + gn] = v;
                    } else {
                        v += bias[gn];
                        if (ACT == 1) v = gelu_tanh(v);
                        if (DUAL) {
                            __nv_bfloat16 hi, lo; split_bf16(v, hi, lo);
                            __nv_bfloat16* o = Cd + (size_t)gm * (2*N);
                            o[gn] = hi; o[N + gn] = lo;
                        } else {
                            C[(size_t)gm * N + gn] = v;
                        }
                    }
                }
            }
        }
    }
}

// ---------------- flash-style Tversky attention (dual-out) ----------------
__global__ __launch_bounds__(256)
void attn_flash_kernel(const float* __restrict__ qkv, __nv_bfloat16* __restrict__ odual) {
    int it = blockIdx.x, h = blockIdx.y, b = blockIdx.z;
    int i0 = it * 64;
    __shared__ float Qs[64][68];
    __shared__ float Ks[64][36];
    __shared__ float Vs[32][68];
    __shared__ float Ps[64][36];
    __shared__ float qs_s[64], ks_s[32], den[64];
    int tid = threadIdx.x;

    #pragma unroll
    for (int p = 0; p < 4; p++) {
        int idx = tid + p*256;
        int i = idx >> 4, d4 = (idx & 15) * 4;
        int gi = i0 + i;
        float4 q = make_float4(0.f,0.f,0.f,0.f);
        if (gi < TT) q = *(const float4*)(qkv + (size_t)(b*TT + gi)*(3*EE) + h*DHH + d4);
        Qs[d4+0][i] = fmaxf(q.x, 0.f);
        Qs[d4+1][i] = fmaxf(q.y, 0.f);
        Qs[d4+2][i] = fmaxf(q.z, 0.f);
        Qs[d4+3][i] = fmaxf(q.w, 0.f);
    }
    if (tid < 64) den[tid] = 0.f;
    __syncthreads();
    if (tid < 64) {
        float s = 0.f;
        #pragma unroll
        for (int d = 0; d < 64; d++) s += Qs[d][tid];
        qs_s[tid] = s;
    }

    float o[4][4];
    #pragma unroll
    for (int r = 0; r < 4; r++)
        #pragma unroll
        for (int c = 0; c < 4; c++) o[r][c] = 0.f;

    int tj = tid & 15, ti = tid >> 4;

    for (int jc = 0; jc < 7; jc++) {
        int j0 = jc * 32;
        __syncthreads();
        #pragma unroll
        for (int p = 0; p < 2; p++) {
            int idx = tid + p*256;
            int j = idx >> 4, d4 = (idx & 15) * 4;
            int gj = j0 + j;
            float4 kv = make_float4(0.f,0.f,0.f,0.f);
            float4 vv = make_float4(0.f,0.f,0.f,0.f);
            if (gj < TT) {
                const float* rowp = qkv + (size_t)(b*TT + gj)*(3*EE) + h*DHH;
                kv = *(const float4*)(rowp + EE + d4);
                vv = *(const float4*)(rowp + 2*EE + d4);
            }
            Ks[d4+0][j] = fmaxf(kv.x, 0.f);
            Ks[d4+1][j] = fmaxf(kv.y, 0.f);
            Ks[d4+2][j] = fmaxf(kv.z, 0.f);
            Ks[d4+3][j] = fmaxf(kv.w, 0.f);
            *(float4*)&Vs[j][d4] = vv;
        }
        __syncthreads();
        if (tid < 32) {
            float s = 0.f;
            #pragma unroll
            for (int d = 0; d < 64; d++) s += Ks[d][tid];
            ks_s[tid] = s;
        }
        __syncthreads();

        float m[4][2];
        #pragma unroll
        for (int r = 0; r < 4; r++) { m[r][0] = 0.f; m[r][1] = 0.f; }
        #pragma unroll 8
        for (int d = 0; d < 64; d++) {
            float4 qv = *(const float4*)&Qs[d][ti*4];
            float2 kv = *(const float2*)&Ks[d][tj*2];
            m[0][0] += fminf(qv.x, kv.x); m[0][1] += fminf(qv.x, kv.y);
            m[1][0] += fminf(qv.y, kv.x); m[1][1] += fminf(qv.y, kv.y);
            m[2][0] += fminf(qv.z, kv.x); m[2][1] += fminf(qv.z, kv.y);
            m[3][0] += fminf(qv.w, kv.x); m[3][1] += fminf(qv.w, kv.y);
        }
        #pragma unroll
        for (int r = 0; r < 4; r++) {
            int i = ti*4 + r;
            int gi = i0 + i;
            #pragma unroll
            for (int e = 0; e < 2; e++) {
                int j = tj*2 + e;
                int gj = j0 + j;
                float sc = 2.f * m[r][e] / (qs_s[i] + ks_s[j] + 2e-8f);
                Ps[i][j] = (gi < TT && gj < TT) ? expf(sc) : 0.f;
            }
        }
        __syncthreads();
        if (tid < 64) {
            float s = 0.f;
            #pragma unroll
            for (int j = 0; j < 32; j++) s += Ps[tid][j];
            den[tid] += s;
        }
        #pragma unroll 4
        for (int jj = 0; jj < 32; jj++) {
            float4 vv = *(const float4*)&Vs[jj][tj*4];
            #pragma unroll
            for (int r = 0; r < 4; r++) {
                float pw = Ps[ti*4 + r][jj];
                o[r][0] += pw * vv.x;
                o[r][1] += pw * vv.y;
                o[r][2] += pw * vv.z;
                o[r][3] += pw * vv.w;
            }
        }
    }
    __syncthreads();

    #pragma unroll
    for (int r = 0; r < 4; r++) {
        int i = ti*4 + r;
        int gi = i0 + i;
        if (gi >= TT) continue;
        float dn = den[i];
        __nv_bfloat16* op = odual + (size_t)(b*TT + gi) * (2*EE);
        #pragma unroll
        for (int c = 0; c < 4; c++) {
            float val = o[r][c] / dn;
            int col = h*DHH + tj*4 + c;
            __nv_bfloat16 hi, lo; split_bf16(val, hi, lo);
            op[col] = hi; op[EE + col] = lo;
        }
    }
}

// ---------------- small fp32 GEMM (head only) ----------------
__global__ void head_gemm_kernel(const float* __restrict__ A, const float* __restrict__ B,
                                 const float* __restrict__ bias, float* __restrict__ C,
                                 int M, int N, int K) {
    const int BN = 64, BK = 16;
    __shared__ float As[BK][8];
    __shared__ float Bs[BK][BN + 1];
    int bn = blockIdx.x * BN;
    int tid = threadIdx.x;
    int tx = tid & 15, ty = tid >> 4;
    float acc[4] = {0.f, 0.f, 0.f, 0.f};
    for (int k0 = 0; k0 < K; k0 += BK) {
        if (tid < BK * M) {
            int m = tid / BK, kk = tid % BK;
            As[kk][m] = A[(size_t)m * K + k0 + kk];
        }
        #pragma unroll
        for (int i = 0; i < 4; i++) {
            int s = tid + i * 256;
            int kk = s >> 6, n = s & 63;
            int gn = bn + n;
            Bs[kk][n] = (gn < N) ? B[(size_t)(k0 + kk) * N + gn] : 0.f;
        }
        __syncthreads();
        if (ty < M) {
            #pragma unroll
            for (int kk = 0; kk < BK; kk++) {
                float a = As[kk][ty];
                #pragma unroll
                for (int j = 0; j < 4; j++)
                    acc[j] = fmaf(a, Bs[kk][tx*4 + j], acc[j]);
            }
        }
        __syncthreads();
    }
    if (ty < M) {
        #pragma unroll
        for (int j = 0; j < 4; j++) {
            int gn = bn + tx*4 + j;
            if (gn < N) C[(size_t)ty * N + gn] = acc[j] + bias[gn];
        }
    }
}

// ---------------- host launcher ----------------
extern "C" void kernel_launch(void* const* d_in, const int* in_sizes, int n_in,
                              void* d_out, int out_size) {
    const float* x         = (const float*)d_in[0];
    const float* conv_w    = (const float*)d_in[1];
    const float* conv_b    = (const float*)d_in[2];
    const float* pos_embed = (const float*)d_in[3];
    const float* cls_token = (const float*)d_in[4];
    const float* ln1_w     = (const float*)d_in[5];
    const float* ln1_b     = (const float*)d_in[6];
    const float* attn_w    = (const float*)d_in[7];
    const float* attn_b    = (const float*)d_in[8];
    const float* proj_w    = (const float*)d_in[9];
    const float* proj_b    = (const float*)d_in[10];
    const float* ln2_w     = (const float*)d_in[11];
    const float* ln2_b     = (const float*)d_in[12];
    const float* fc1_w     = (const float*)d_in[13];
    const float* fc1_b     = (const float*)d_in[14];
    const float* fc2_w     = (const float*)d_in[15];
    const float* fc2_b     = (const float*)d_in[16];
    const float* lnf_w     = (const float*)d_in[17];
    const float* lnf_b     = (const float*)d_in[18];
    const float* head_w    = (const float*)d_in[19];
    const float* head_b    = (const float*)d_in[20];
    float* out = (float*)d_out;

    float *p_h, *p_qkv, *p_cls, *p_part;
    __nv_bfloat16 *p_abf, *p_lntri, *p_wall;
    cudaGetSymbolAddress((void**)&p_h, g_h);
    cudaGetSymbolAddress((void**)&p_qkv, g_qkv);
    cudaGetSymbolAddress((void**)&p_cls, g_cls);
    cudaGetSymbolAddress((void**)&p_part, g_part);
    cudaGetSymbolAddress((void**)&p_abf, g_abf);
    cudaGetSymbolAddress((void**)&p_lntri, g_lntri);
    cudaGetSymbolAddress((void**)&p_wall, g_wall);

    const __nv_bfloat16* wPatch = p_wall;
    const __nv_bfloat16* wQKV[LL], *wProj[LL], *wFc1[LL], *wFc2[LL];
    for (int l = 0; l < LL; l++) {
        const __nv_bfloat16* base = p_wall + OFF_L0 + (size_t)l * SZ_LAYER_D;
        wQKV[l] = base;
        wProj[l] = base + SZ_QKV_D;
        wFc1[l] = base + SZ_QKV_D + SZ_PROJ_D;
        wFc2[l] = base + SZ_QKV_D + SZ_PROJ_D + SZ_FC1_D;
    }

    // ---- prep ----
    {
        int total = BB*NPAT*KPATCH;
        im2col_dual_kernel<<<(total + 255)/256, 256>>>(x, p_abf);
        int wtot = 589824 + 2*7077888;
        wconv_all_kernel<<<(wtot + 255)/256, 256>>>(conv_w, attn_w, proj_w, fc1_w, fc2_w);
    }

    // ---- patch embedding GEMM (split-4) + fused epilogue/LN1 ----
    {
        dim3 g(EE/128, (BB*NPAT + 127)/128, 4);
        mma_gemm<0, true, false><<<g, 256>>>(
            p_abf, wPatch, nullptr, p_part, nullptr, BB*NPAT, EE, KPATCH, (3*KPATCH)/4);
        patch_ln_kernel<<<MROWS, 256>>>(p_part, conv_b, pos_embed, cls_token, ln1_w, ln1_b);
    }

    // ---- transformer layers ----
    for (int l = 0; l < LL; l++) {
        const float* ab  = attn_b + (size_t)l * 3 * EE;
        const float* pb  = proj_b + (size_t)l * EE;
        const float* lw2 = ln2_w + (size_t)l * EE;
        const float* lb2 = ln2_b + (size_t)l * EE;
        const float* f1b = fc1_b + (size_t)l * DFF_;
        const float* f2b = fc2_b + (size_t)l * EE;

        // qkv: [788, 2304(logical K=3*768)] x wQKV -> fp32 qkv
        {
            dim3 g((3*EE)/128, (MROWS + 127)/128, 1);
            mma_gemm<0, false, false><<<g, 256>>>(
                p_lntri, wQKV[l], ab, p_qkv, nullptr, MROWS, 3*EE, EE, 3*EE);
        }
        attn_flash_kernel<<<dim3(4, NHH, BB), 256>>>(p_qkv, p_abf);
        // proj split-4 + fused reduce/res/LN2
        {
            dim3 g(EE/128, (MROWS + 127)/128, 4);
            mma_gemm<0, true, false><<<g, 256>>>(
                p_abf, wProj[l], nullptr, p_part, nullptr, MROWS, EE, EE, (3*EE)/4);
            fuse_res_ln_kernel<4, true><<<MROWS, 256>>>(p_part, pb, lw2, lb2);
        }
        // fc1 (gelu, dual out)
        {
            dim3 g(DFF_/128, (MROWS + 127)/128, 1);
            mma_gemm<1, false, true><<<g, 256>>>(
                p_lntri, wFc1[l], f1b, nullptr, p_abf, MROWS, DFF_, EE, 3*EE);
        }
        // fc2 split-4 + fused reduce/res (+ LN1 of next layer)
        {
            dim3 g(EE/128, (MROWS + 127)/128, 4);
            mma_gemm<0, true, false><<<g, 256>>>(
                p_abf, wFc2[l], nullptr, p_part, nullptr, MROWS, EE, DFF_, (3*DFF_)/4);
            if (l + 1 < LL) {
                fuse_res_ln_kernel<4, true><<<MROWS, 256>>>(
                    p_part, f2b, ln1_w + (size_t)(l+1)*EE, ln1_b + (size_t)(l+1)*EE);
            } else {
                fuse_res_ln_kernel<4, false><<<MROWS, 256>>>(p_part, f2b, nullptr, nullptr);
            }
        }
    }

    // ---- final LN (cls rows) + head ----
    ln_kernel<<<BB, 256>>>(p_h, lnf_w, lnf_b, p_cls, EE, (size_t)TT*EE, EE);
    head_gemm_kernel<<<(OUTC + 63)/64, 256>>>(p_cls, head_w, head_b, out, BB, OUTC, EE);
}